// round 12
// baseline (speedup 1.0000x reference)
#include <cuda_runtime.h>
#include <math.h>
#include <stdint.h>

#define H    160
#define H3   480
#define CC   200
#define TT   20
#define NCH  10
#define NL   160
#define NCLS 16
#define HSS  20          /* h-slice per CTA (8-way split) */
#define RPC  60          /* rows per CTA = 3*HSS */
#define NT   512
#define NBLK 120
#define FULL 160

#define NFLAGS ((NL + 1) * NCH + 1)
#define GDONE_IDX ((NL + 1) * NCH)
#define DONE_IDX(l, t) ((l) * NCH + (t))

/* packed weights: g3 wih chunks [0,1280), g3 whh chunks [1280,2560), branch after */
#define G3_F4   (2560 * 2400)          /* 6,144,000 float4 */
#define BR_F4   (20 * 9600)
#define PACK_F4 (G3_F4 + BR_F4)

__device__ float4 g_pack[PACK_F4];
__device__ float  g_S[(NL + 1) * NCH * H];
__device__ float  g_xl[H];
__device__ int    g_flags[NFLAGS];

typedef unsigned long long ull;

__device__ __forceinline__ float sigm(float v)   { return __fdividef(1.f, 1.f + __expf(-v)); }
__device__ __forceinline__ float tanh_f(float v) { return __fdividef(2.f, 1.f + __expf(-2.f * v)) - 1.f; }

__device__ __forceinline__ void poll_ge(const int* f, int tgt) {
    int v;
    do {
        asm volatile("ld.acquire.gpu.s32 %0, [%1];" : "=r"(v) : "l"(f) : "memory");
    } while (v < tgt);
}
__device__ __forceinline__ void red_release(int* f, int val) {
    asm volatile("red.release.gpu.add.s32 [%0], %1;" :: "l"(f), "r"(val) : "memory");
}

__device__ __forceinline__ uint32_t smem_u32(const void* p) {
    uint32_t a;
    asm("{ .reg .u64 t; cvta.to.shared.u64 t, %1; cvt.u32.u64 %0, t; }" : "=r"(a) : "l"(p));
    return a;
}
__device__ __forceinline__ void st_cluster_f32(uint32_t laddr, int rank, float v) {
    uint32_t r;
    asm("mapa.shared::cluster.u32 %0, %1, %2;" : "=r"(r) : "r"(laddr), "r"(rank));
    asm volatile("st.shared::cluster.f32 [%0], %1;" :: "r"(r), "f"(v) : "memory");
}
__device__ __forceinline__ void mbar_init(uint32_t addr, uint32_t count) {
    asm volatile("mbarrier.init.shared.b64 [%0], %1;" :: "r"(addr), "r"(count) : "memory");
}
__device__ __forceinline__ void mbar_arrive_rank(uint32_t addr, int rank) {
    uint32_t r;
    asm("mapa.shared::cluster.u32 %0, %1, %2;" : "=r"(r) : "r"(addr), "r"(rank));
    asm volatile("mbarrier.arrive.release.cluster.shared::cluster.b64 _, [%0];" :: "r"(r) : "memory");
}
__device__ __forceinline__ void mbar_arrive_local(uint32_t addr) {
    asm volatile("mbarrier.arrive.release.cta.shared.b64 _, [%0];" :: "r"(addr) : "memory");
}
__device__ __forceinline__ void mbar_wait(uint32_t addr, int parity) {
    asm volatile(
        "{\n\t.reg .pred P;\n\t"
        "WL_%=:\n\t"
        "mbarrier.try_wait.parity.acquire.cluster.shared::cta.b64 P, [%0], %1;\n\t"
        "@!P bra WL_%=;\n\t}"
        :: "r"(addr), "r"(parity) : "memory");
}
#define CLUSTER_SYNC() do { \
    asm volatile("barrier.cluster.arrive.aligned;" ::: "memory"); \
    asm volatile("barrier.cluster.wait.aligned;"   ::: "memory"); } while (0)
#define BAR_DOT()        asm volatile("bar.sync 1, 480;" ::: "memory")

__device__ __forceinline__ ull pack2(float x, float y) {
    ull u; asm("mov.b64 %0, {%1, %2};" : "=l"(u) : "f"(x), "f"(y)); return u;
}
__device__ __forceinline__ void fma2(ull& acc, ull a, ull b) {
    asm("fma.rn.f32x2 %0, %1, %2, %0;" : "+l"(acc) : "l"(a), "l"(b));
}
__device__ __forceinline__ float upsum(ull a0, ull a1) {
    float l0, h0, l1, h1;
    asm("mov.b64 {%0, %1}, %2;" : "=f"(l0), "=f"(h0) : "l"(a0));
    asm("mov.b64 {%0, %1}, %2;" : "=f"(l1), "=f"(h1) : "l"(a1));
    return (l0 + h0) + (l1 + h1);
}

/* ---------- pack kernel (also zeroes flags) ---------- */
__global__ void pack_kernel(const float4* __restrict__ wih,
                            const float4* __restrict__ whh,
                            const float4* __restrict__ bwhh) {
    int id = blockIdx.x * blockDim.x + threadIdx.x;
    if (id < NFLAGS) g_flags[id] = 0;
    if (id >= PACK_F4) return;
    float4 v;
    if (id < G3_F4) {
        int chunkid = id / 2400;                 /* 0..2559 */
        int within  = id - chunkid * 2400;
        int i4 = within / 480, tid = within - i4 * 480;
        int m  = chunkid / 1280;
        int lc = chunkid - m * 1280;
        int l = lc >> 3, c = lc & 7;
        int q = tid >> 3, qk = tid & 7;
        int jrow = (q / HSS) * H + c * HSS + (q % HSS);
        int k4 = qk * 5 + i4;
        const float4* src = (m == 0) ? wih : whh;
        v = src[((size_t)l * H3 + jrow) * 40 + k4];
    } else {
        int id2    = id - G3_F4;
        int chunk  = id2 / 9600;
        int within = id2 - chunk * 9600;
        int i4 = within / 480, tid = within - i4 * 480;
        int b = chunk >> 1, hh = chunk & 1;
        int qk2 = tid & 1, gi = tid >> 1;
        int g = gi / 80, ip = gi - g * 80;
        int j = g * H + hh * 80 + ip;
        int k4 = qk2 * 20 + i4;
        v = bwhh[((size_t)b * H3 + j) * 40 + k4];
    }
    g_pack[id] = v;
}

/* ---------- main persistent kernel ---------- */
__global__ void __launch_bounds__(NT, 1) __cluster_dims__(8, 1, 1)
spectral_kernel(
    const float* __restrict__ x,
    const float* __restrict__ b_wih, const float* __restrict__ b_bih,
    const float* __restrict__ b_bhh,
    const float* __restrict__ gw_ih, const float* __restrict__ gw_hh,
    const float* __restrict__ gb_ih, const float* __restrict__ gb_hh,
    const float* __restrict__ g3_bih, const float* __restrict__ g3_bhh,
    const float* __restrict__ bn_gamma, const float* __restrict__ bn_beta,
    const float* __restrict__ bn_mean, const float* __restrict__ bn_var,
    const float* __restrict__ fc_w, const float* __restrict__ fc_b,
    const float* __restrict__ reg_w, const float* __restrict__ reg_b,
    float* __restrict__ out)
{
    extern __shared__ float sm[];
    const int tid = threadIdx.x;
    const int blk = blockIdx.x;
    const float4* packW = g_pack;
    const bool dotw = (tid < 480);

    /* ============ g3 wavefront: blocks 0..79 (cluster of 8 = time group) === */
    if (blk < 80) {
        const int t = blk >> 3;
        const int c = blk & 7;
        const int q  = tid >> 3;          /* 0..59  row within CTA slice */
        const int qk = tid & 7;           /* 0..7   k-eighth (20 elems)  */
        const int jrow = dotw ? ((q / HSS) * H + c * HSS + (q % HSS)) : 0;

        const uint32_t mb = smem_u32(sm);  /* mbarrier, 8 bytes */
        float* xin2 = sm + 4;              /* [2][H] (16B-aligned) */
        float* hbuf = xin2 + 2 * H;        /* [2][H] double-buffered h_prev */
        float* xps  = hbuf + 2 * H;        /* [RPC]  */
        float* hps  = xps + RPC;           /* [RPC]  */
        const uint32_t xin_base = smem_u32(xin2);

        if (tid == 0) mbar_init(mb, 161);  /* 8*20 remote + 1 local */
        if (tid < 2 * H) hbuf[tid] = 0.f;
        __syncthreads();
        CLUSTER_SYNC();                    /* mbars visible cluster-wide */

        ull Wx[10], Wh[10];
        float bih_c = 0.f, bhh_c = 0.f;
        if (dotw) {   /* preload wih(0), whh(0), biases(0) */
            size_t bx = (size_t)(0 * 8 + c) * 2400 + tid;
            size_t bh = (size_t)(1280 + 0 * 8 + c) * 2400 + tid;
#pragma unroll
            for (int i4 = 0; i4 < 5; ++i4) {
                float4 f = __ldg(&packW[bx + i4 * 480]);
                Wx[2 * i4] = pack2(f.x, f.y); Wx[2 * i4 + 1] = pack2(f.z, f.w);
                float4 g = __ldg(&packW[bh + i4 * 480]);
                Wh[2 * i4] = pack2(g.x, g.y); Wh[2 * i4 + 1] = pack2(g.z, g.w);
            }
            if (qk == 0) { bih_c = __ldg(&g3_bih[jrow]); bhh_c = __ldg(&g3_bhh[jrow]); }
        }

        /* initial staging: xin[0] from branch; hbuf[0] = S(1,t-1) */
        if (tid == 0) poll_ge(&g_flags[DONE_IDX(0, t)], FULL);
        if (t > 0 && tid == 480) poll_ge(&g_flags[DONE_IDX(1, t - 1)], FULL);
        __syncthreads();
        if (tid < 40)
            *(float4*)&xin2[tid * 4] = __ldcg((const float4*)&g_S[t * H + tid * 4]);
        if (t > 0 && !dotw) {
            const int lane = tid - 480;
            const float4* src = (const float4*)&g_S[((size_t)1 * NCH + (t - 1)) * H];
            ((float4*)hbuf)[lane] = __ldcg(src + lane);
            if (lane < 8) ((float4*)hbuf)[32 + lane] = __ldcg(src + 32 + lane);
        }
        __syncthreads();

        for (int l = 0; l < NL; ++l) {
            const int cur = l & 1, nxt = cur ^ 1;

            if (dotw) {
                /* fused X + H dots */
                const float* xv  = xin2 + cur * H + qk * HSS;
                const float* hv0 = hbuf + cur * H + qk * HSS;
                ull a0 = 0, a1 = 0, b0 = 0, b1 = 0;
#pragma unroll
                for (int i4 = 0; i4 < 5; ++i4) {
                    ulonglong2 xh = *(const ulonglong2*)(xv + i4 * 4);
                    ulonglong2 hh = *(const ulonglong2*)(hv0 + i4 * 4);
                    fma2(a0, Wx[2 * i4], xh.x); fma2(a1, Wx[2 * i4 + 1], xh.y);
                    fma2(b0, Wh[2 * i4], hh.x); fma2(b1, Wh[2 * i4 + 1], hh.y);
                }
                float ax = upsum(a0, a1);
                float ah = upsum(b0, b1);
                ax += __shfl_xor_sync(0xffffffffu, ax, 1);
                ah += __shfl_xor_sync(0xffffffffu, ah, 1);
                ax += __shfl_xor_sync(0xffffffffu, ax, 2);
                ah += __shfl_xor_sync(0xffffffffu, ah, 2);
                ax += __shfl_xor_sync(0xffffffffu, ax, 4);
                ah += __shfl_xor_sync(0xffffffffu, ah, 4);
                if (qk == 0) { xps[q] = ax + bih_c; hps[q] = ah + bhh_c; }
                BAR_DOT();                       /* dots -> gate (480 threads) */

                if (tid < HSS) {
                    const int i = tid;
                    float hp_i = hbuf[cur * H + c * HSS + i];
                    float r = sigm(xps[i]            + hps[i]);
                    float z = sigm(xps[HSS + i]      + hps[HSS + i]);
                    float n = tanh_f(xps[2*HSS + i]  + r * hps[2*HSS + i]);
                    float hn = (1.f - z) * n + z * hp_i;
                    __stcg(&g_S[((size_t)(l + 1) * NCH + t) * H + c * HSS + i], hn);
                    red_release(&g_flags[DONE_IDX(l + 1, t)], 1);
                    uint32_t a3 = xin_base + (uint32_t)(nxt * H + c * HSS + i) * 4u;
#pragma unroll
                    for (int r2 = 0; r2 < 8; ++r2) st_cluster_f32(a3, r2, hn);
#pragma unroll
                    for (int r2 = 0; r2 < 8; ++r2) mbar_arrive_rank(mb, r2);
                }
                /* prefetch weights + biases for l+1 BEFORE the wait */
                if (l + 1 < NL) {
                    size_t bx = (size_t)((l + 1) * 8 + c) * 2400 + tid;
                    size_t bh = (size_t)(1280 + (l + 1) * 8 + c) * 2400 + tid;
#pragma unroll
                    for (int i4 = 0; i4 < 5; ++i4) {
                        float4 f = __ldg(&packW[bx + i4 * 480]);
                        Wx[2 * i4] = pack2(f.x, f.y); Wx[2 * i4 + 1] = pack2(f.z, f.w);
                        float4 g = __ldg(&packW[bh + i4 * 480]);
                        Wh[2 * i4] = pack2(g.x, g.y); Wh[2 * i4 + 1] = pack2(g.z, g.w);
                    }
                    if (qk == 0) {
                        bih_c = __ldg(&g3_bih[(l + 1) * H3 + jrow]);
                        bhh_c = __ldg(&g3_bhh[(l + 1) * H3 + jrow]);
                    }
                }
                mbar_wait(mb, l & 1);
            } else {
                /* warp15: prefetch h for layer l+1 into hbuf[nxt] */
                if (t > 0 && l + 2 <= NL) {
                    if (tid == 480) poll_ge(&g_flags[DONE_IDX(l + 2, t - 1)], FULL);
                    __syncwarp();
                    const int lane = tid - 480;
                    const float4* src =
                        (const float4*)&g_S[((size_t)(l + 2) * NCH + (t - 1)) * H];
                    ((float4*)(hbuf + nxt * H))[lane] = __ldcg(src + lane);
                    if (lane < 8)
                        ((float4*)(hbuf + nxt * H))[32 + lane] = __ldcg(src + 32 + lane);
                    __syncwarp();
                }
                if (tid == 480) mbar_arrive_local(mb);
                mbar_wait(mb, l & 1);
            }
        }
        return;
    }

    /* ============ global GRU: blocks 80..87, one cluster, 8-way ============ */
    if (blk < 88) {
        const int c = blk - 80;

        const uint32_t mb = smem_u32(sm);
        float* xp_s  = sm + 4;                   /* [CC*RPC] 48KB */
        float* bhh_s = xp_s + CC * RPC;          /* [RPC]    */
        float* h2    = bhh_s + RPC;              /* [2][H]   */
        float* hpb   = h2 + 2 * H;               /* [RPC]    */
        const uint32_t h2_base = smem_u32(h2);

        if (tid == 0) mbar_init(mb, 160);        /* 8*20 remote */

        const int q2 = tid >> 3;
        const int qk = tid & 7;
        const int j  = dotw ? ((q2 / HSS) * H + c * HSS + (q2 % HSS)) : 0;

        ull W[10];
        if (dotw) {
            const float4* wr = (const float4*)&gw_hh[(size_t)j * H + qk * HSS];
#pragma unroll
            for (int i4 = 0; i4 < 5; ++i4) {
                float4 f = __ldg(wr + i4);
                W[2 * i4] = pack2(f.x, f.y); W[2 * i4 + 1] = pack2(f.z, f.w);
            }
        }
        for (int idx = tid; idx < CC * RPC; idx += NT) {
            int s = idx / RPC, qq = idx - s * RPC;
            int jj = (qq / HSS) * H + c * HSS + (qq % HSS);
            xp_s[idx] = x[s] * gw_ih[jj] + gb_ih[jj];
        }
        if (tid < RPC) {
            int jj = (tid / HSS) * H + c * HSS + (tid % HSS);
            bhh_s[tid] = gb_hh[jj];
        }
        if (tid < 2 * H) h2[tid] = 0.f;
        __syncthreads();
        CLUSTER_SYNC();

        float hsum = 0.f;
        for (int s = 0; s < CC; ++s) {
            const int cur = s & 1, nxt = cur ^ 1;
            if (dotw) {
                const float* hv0 = h2 + cur * H + qk * HSS;
                ull a0 = 0, a1 = 0;
#pragma unroll
                for (int i4 = 0; i4 < 5; ++i4) {
                    ulonglong2 hv = *(const ulonglong2*)(hv0 + i4 * 4);
                    fma2(a0, W[2 * i4], hv.x);
                    fma2(a1, W[2 * i4 + 1], hv.y);
                }
                float a = upsum(a0, a1);
                a += __shfl_xor_sync(0xffffffffu, a, 1);
                a += __shfl_xor_sync(0xffffffffu, a, 2);
                a += __shfl_xor_sync(0xffffffffu, a, 4);
                if (qk == 0) hpb[q2] = a + bhh_s[q2];
            }
            __syncthreads();
            if (tid < HSS) {
                const float* xpt = xp_s + s * RPC;
                const int i = tid;
                float r = sigm(xpt[i]            + hpb[i]);
                float z = sigm(xpt[HSS + i]      + hpb[HSS + i]);
                float n = tanh_f(xpt[2*HSS + i]  + r * hpb[2*HSS + i]);
                float hn = (1.f - z) * n + z * h2[cur * H + c * HSS + i];
                hsum += hn;
                uint32_t a2 = h2_base + (uint32_t)(nxt * H + c * HSS + i) * 4u;
#pragma unroll
                for (int r2 = 0; r2 < 8; ++r2) st_cluster_f32(a2, r2, hn);
#pragma unroll
                for (int r2 = 0; r2 < 8; ++r2) mbar_arrive_rank(mb, r2);
            }
            mbar_wait(mb, s & 1);
        }
        if (tid < HSS) {
            __stcg(&g_xl[c * HSS + tid], hsum * (1.f / CC));
            red_release(&g_flags[GDONE_IDX], 1);
        }
        return;
    }

    /* ============ branch GRUs: blocks 88..107 (2 CTAs/branch, 4 pairs/cluster) */
    if (blk < 108) {
        const int pairblk = blk - 88;
        const int b    = pairblk >> 1;
        const int hh   = pairblk & 1;
        const int rank = pairblk & 7;

        float* xp_s = sm;                      /* [TT*240]  */
        float* h2   = xp_s + TT * 240;         /* [2][H]    */
        float* hp_s = h2 + 2 * H;              /* [240]     */
        const uint32_t h2b = smem_u32(h2);

        const int qk2 = tid & 1;
        const int gi  = tid >> 1;
        const int g   = gi / 80;
        const int ip  = gi - g * 80;
        const int jrow = dotw ? (g * H + hh * 80 + ip) : 0;

        ull W[40];
        if (dotw) {
            size_t base = (size_t)G3_F4 + (size_t)(b * 2 + hh) * 9600 + tid;
#pragma unroll
            for (int i4 = 0; i4 < 20; ++i4) {
                float4 f = __ldg(&packW[base + i4 * 480]);
                W[2 * i4] = pack2(f.x, f.y); W[2 * i4 + 1] = pack2(f.z, f.w);
            }
        }
        float bhh_v = 0.f;
        if (dotw && qk2 == 0) bhh_v = __ldg(&b_bhh[b * H3 + jrow]);

        for (int idx = tid; idx < TT * 240; idx += NT) {
            int tt = idx / 240, lr = idx - tt * 240;
            int jj = (lr / 80) * H + hh * 80 + (lr % 80);
            xp_s[idx] = x[b * TT + tt] * b_wih[b * H3 + jj] + b_bih[b * H3 + jj];
        }
        if (tid < 2 * H) h2[tid] = 0.f;
        __syncthreads();
        CLUSTER_SYNC();                                    /* sync #1 */

        for (int tt = 0; tt < TT; ++tt) {
            const int cur = tt & 1, nxt = cur ^ 1;
            if (dotw) {
                const float* hv0 = h2 + cur * H + qk2 * 80;
                ull a0 = 0, a1 = 0;
#pragma unroll
                for (int i4 = 0; i4 < 20; ++i4) {
                    ulonglong2 hv = *(const ulonglong2*)(hv0 + i4 * 4);
                    fma2(a0, W[2 * i4], hv.x);
                    fma2(a1, W[2 * i4 + 1], hv.y);
                }
                float a = upsum(a0, a1);
                a += __shfl_xor_sync(0xffffffffu, a, 1);
                if (qk2 == 0) hp_s[g * 80 + ip] = a + bhh_v;
            }
            __syncthreads();

            if (dotw && qk2 == 0 && gi < 80) {
                const int i = gi;
                const float* xpt = xp_s + tt * 240;
                float r = sigm(xpt[i]          + hp_s[i]);
                float z = sigm(xpt[80 + i]     + hp_s[80 + i]);
                float n = tanh_f(xpt[160 + i]  + r * hp_s[160 + i]);
                float hn = (1.f - z) * n + z * h2[cur * H + hh * 80 + i];
                uint32_t a3 = h2b + (uint32_t)(nxt * H + hh * 80 + i) * 4u;
                st_cluster_f32(a3, rank, hn);
                st_cluster_f32(a3, rank ^ 1, hn);
            }
            CLUSTER_SYNC();                                /* syncs #2..#21 */
        }
        if (tid < 80) {
            __stcg(&g_S[b * H + hh * 80 + tid], h2[0 * H + hh * 80 + tid]);
            red_release(&g_flags[DONE_IDX(0, b)], 1);
        }
        CLUSTER_SYNC();                                    /* sync #22 */
        return;
    }

    /* ============ branch-cluster fillers: blocks 108..111 ================== */
    if (blk < 112) {
        for (int i = 0; i < TT + 2; ++i) CLUSTER_SYNC();   /* match 22 syncs */
        return;
    }

    /* ============ epilogue: block 112 (113..119 idle, no cluster ops) ====== */
    if (blk == 112) {
        if (tid == 0) {
            for (int tt = 0; tt < NCH; ++tt) poll_ge(&g_flags[DONE_IDX(NL, tt)], FULL);
            poll_ge(&g_flags[GDONE_IDX], FULL);
        }
        __syncthreads();

        float* xr = sm;
        if (tid < H) {
            float m = 0.f;
#pragma unroll
            for (int tt = 0; tt < NCH; ++tt) m += __ldcg(&g_S[(NL * NCH + tt) * H + tid]);
            m *= (1.f / NCH);
            m = fmaxf(m, 0.f);
            float xnew = __ldcg(&g_xl[tid]) * m;
            float xb = (xnew - bn_mean[tid]) * rsqrtf(bn_var[tid] + 1e-5f)
                       * bn_gamma[tid] + bn_beta[tid];
            xr[tid] = fmaxf(xb, 0.f);
        }
        __syncthreads();

        if (tid < NCLS + CC) {
            const float* wrow; float bias;
            if (tid < NCLS) { wrow = fc_w + tid * H;           bias = fc_b[tid]; }
            else            { wrow = reg_w + (tid - NCLS) * H; bias = reg_b[tid - NCLS]; }
            float a = bias;
#pragma unroll 10
            for (int k = 0; k < H; ++k) a += wrow[k] * xr[k];
            out[tid] = a;
        }
        return;
    }
}

extern "C" void kernel_launch(void* const* d_in, const int* in_sizes, int n_in,
                              void* d_out, int out_size) {
    const float* x        = (const float*)d_in[0];
    const float* b_wih    = (const float*)d_in[1];
    const float* b_whh    = (const float*)d_in[2];
    const float* b_bih    = (const float*)d_in[3];
    const float* b_bhh    = (const float*)d_in[4];
    const float* gw_ih    = (const float*)d_in[5];
    const float* gw_hh    = (const float*)d_in[6];
    const float* gb_ih    = (const float*)d_in[7];
    const float* gb_hh    = (const float*)d_in[8];
    const float* g3_wih   = (const float*)d_in[9];
    const float* g3_whh   = (const float*)d_in[10];
    const float* g3_bih   = (const float*)d_in[11];
    const float* g3_bhh   = (const float*)d_in[12];
    const float* bn_gamma = (const float*)d_in[13];
    const float* bn_beta  = (const float*)d_in[14];
    const float* bn_mean  = (const float*)d_in[15];
    const float* bn_var   = (const float*)d_in[16];
    const float* fc_w     = (const float*)d_in[17];
    const float* fc_b     = (const float*)d_in[18];
    const float* reg_w    = (const float*)d_in[19];
    const float* reg_b    = (const float*)d_in[20];
    float* out = (float*)d_out;

    /* max role smem: global GRU = 4 + CC*RPC + RPC + 2H + RPC floats (~50KB) */
    const int smem_bytes = (4 + CC * RPC + RPC + 2 * H + RPC) * (int)sizeof(float);
    cudaFuncSetAttribute(spectral_kernel,
                         cudaFuncAttributeMaxDynamicSharedMemorySize, smem_bytes);

    pack_kernel<<<(PACK_F4 + 255) / 256, 256>>>(
        (const float4*)g3_wih, (const float4*)g3_whh, (const float4*)b_whh);
    spectral_kernel<<<NBLK, NT, smem_bytes>>>(
        x, b_wih, b_bih, b_bhh,
        gw_ih, gw_hh, gb_ih, gb_hh,
        g3_bih, g3_bhh,
        bn_gamma, bn_beta, bn_mean, bn_var,
        fc_w, fc_b, reg_w, reg_b, out);
}

// round 13
// speedup vs baseline: 1.0049x; 1.0049x over previous
#include <cuda_runtime.h>
#include <math.h>
#include <stdint.h>

#define H    160
#define H3   480
#define CC   200
#define TT   20
#define NCH  10
#define NL   160
#define NCLS 16
#define HSS  20          /* h-slice per CTA (8-way split) */
#define RPC  60          /* rows per CTA = 3*HSS */
#define NT   512
#define NBLK 120
#define FULL 160

#define NFLAGS ((NL + 1) * NCH + 1)
#define GDONE_IDX ((NL + 1) * NCH)
#define DONE_IDX(l, t) ((l) * NCH + (t))

/* packed weights: g3 wih chunks [0,1280), g3 whh chunks [1280,2560), branch after */
#define G3_F4   (2560 * 2400)          /* 6,144,000 float4 */
#define BR_F4   (20 * 9600)
#define PACK_F4 (G3_F4 + BR_F4)

__device__ float4 g_pack[PACK_F4];
__device__ float  g_S[(NL + 1) * NCH * H];
__device__ float  g_xl[H];
__device__ int    g_flags[NFLAGS];

typedef unsigned long long ull;

__device__ __forceinline__ float sigm(float v)   { return __fdividef(1.f, 1.f + __expf(-v)); }
__device__ __forceinline__ float tanh_f(float v) { return __fdividef(2.f, 1.f + __expf(-2.f * v)) - 1.f; }

__device__ __forceinline__ void poll_ge(const int* f, int tgt) {
    int v;
    do {
        asm volatile("ld.acquire.gpu.s32 %0, [%1];" : "=r"(v) : "l"(f) : "memory");
    } while (v < tgt);
}
__device__ __forceinline__ void red_release(int* f, int val) {
    asm volatile("red.release.gpu.add.s32 [%0], %1;" :: "l"(f), "r"(val) : "memory");
}

__device__ __forceinline__ uint32_t smem_u32(const void* p) {
    uint32_t a;
    asm("{ .reg .u64 t; cvta.to.shared.u64 t, %1; cvt.u32.u64 %0, t; }" : "=r"(a) : "l"(p));
    return a;
}
__device__ __forceinline__ void st_cluster_f32(uint32_t laddr, int rank, float v) {
    uint32_t r;
    asm("mapa.shared::cluster.u32 %0, %1, %2;" : "=r"(r) : "r"(laddr), "r"(rank));
    asm volatile("st.shared::cluster.f32 [%0], %1;" :: "r"(r), "f"(v) : "memory");
}
__device__ __forceinline__ void st_cluster_f32x4(uint32_t laddr, int rank, float4 v) {
    uint32_t r;
    asm("mapa.shared::cluster.u32 %0, %1, %2;" : "=r"(r) : "r"(laddr), "r"(rank));
    asm volatile("st.shared::cluster.v4.f32 [%0], {%1, %2, %3, %4};"
                 :: "r"(r), "f"(v.x), "f"(v.y), "f"(v.z), "f"(v.w) : "memory");
}
__device__ __forceinline__ void mbar_init(uint32_t addr, uint32_t count) {
    asm volatile("mbarrier.init.shared.b64 [%0], %1;" :: "r"(addr), "r"(count) : "memory");
}
__device__ __forceinline__ void mbar_arrive_rank(uint32_t addr, int rank) {
    uint32_t r;
    asm("mapa.shared::cluster.u32 %0, %1, %2;" : "=r"(r) : "r"(addr), "r"(rank));
    asm volatile("mbarrier.arrive.release.cluster.shared::cluster.b64 _, [%0];" :: "r"(r) : "memory");
}
__device__ __forceinline__ void mbar_arrive_local(uint32_t addr) {
    asm volatile("mbarrier.arrive.release.cta.shared.b64 _, [%0];" :: "r"(addr) : "memory");
}
__device__ __forceinline__ void mbar_wait(uint32_t addr, int parity) {
    asm volatile(
        "{\n\t.reg .pred P;\n\t"
        "WL_%=:\n\t"
        "mbarrier.try_wait.parity.acquire.cluster.shared::cta.b64 P, [%0], %1;\n\t"
        "@!P bra WL_%=;\n\t}"
        :: "r"(addr), "r"(parity) : "memory");
}
#define CLUSTER_SYNC() do { \
    asm volatile("barrier.cluster.arrive.aligned;" ::: "memory"); \
    asm volatile("barrier.cluster.wait.aligned;"   ::: "memory"); } while (0)
#define BAR_DOT()        asm volatile("bar.sync 1, 480;" ::: "memory")

__device__ __forceinline__ ull pack2(float x, float y) {
    ull u; asm("mov.b64 %0, {%1, %2};" : "=l"(u) : "f"(x), "f"(y)); return u;
}
__device__ __forceinline__ void fma2(ull& acc, ull a, ull b) {
    asm("fma.rn.f32x2 %0, %1, %2, %0;" : "+l"(acc) : "l"(a), "l"(b));
}
__device__ __forceinline__ float upsum(ull a0, ull a1) {
    float l0, h0, l1, h1;
    asm("mov.b64 {%0, %1}, %2;" : "=f"(l0), "=f"(h0) : "l"(a0));
    asm("mov.b64 {%0, %1}, %2;" : "=f"(l1), "=f"(h1) : "l"(a1));
    return (l0 + h0) + (l1 + h1);
}

/* ---------- pack kernel (also zeroes flags) ---------- */
__global__ void pack_kernel(const float4* __restrict__ wih,
                            const float4* __restrict__ whh,
                            const float4* __restrict__ bwhh) {
    int id = blockIdx.x * blockDim.x + threadIdx.x;
    if (id < NFLAGS) g_flags[id] = 0;
    if (id >= PACK_F4) return;
    float4 v;
    if (id < G3_F4) {
        int chunkid = id / 2400;                 /* 0..2559 */
        int within  = id - chunkid * 2400;
        int i4 = within / 480, tid = within - i4 * 480;
        int m  = chunkid / 1280;
        int lc = chunkid - m * 1280;
        int l = lc >> 3, c = lc & 7;
        int q = tid >> 3, qk = tid & 7;
        int jrow = (q / HSS) * H + c * HSS + (q % HSS);
        int k4 = qk * 5 + i4;
        const float4* src = (m == 0) ? wih : whh;
        v = src[((size_t)l * H3 + jrow) * 40 + k4];
    } else {
        int id2    = id - G3_F4;
        int chunk  = id2 / 9600;
        int within = id2 - chunk * 9600;
        int i4 = within / 480, tid = within - i4 * 480;
        int b = chunk >> 1, hh = chunk & 1;
        int qk2 = tid & 1, gi = tid >> 1;
        int g = gi / 80, ip = gi - g * 80;
        int j = g * H + hh * 80 + ip;
        int k4 = qk2 * 20 + i4;
        v = bwhh[((size_t)b * H3 + j) * 40 + k4];
    }
    g_pack[id] = v;
}

/* ---------- main persistent kernel ---------- */
__global__ void __launch_bounds__(NT, 1) __cluster_dims__(8, 1, 1)
spectral_kernel(
    const float* __restrict__ x,
    const float* __restrict__ b_wih, const float* __restrict__ b_bih,
    const float* __restrict__ b_bhh,
    const float* __restrict__ gw_ih, const float* __restrict__ gw_hh,
    const float* __restrict__ gb_ih, const float* __restrict__ gb_hh,
    const float* __restrict__ g3_bih, const float* __restrict__ g3_bhh,
    const float* __restrict__ bn_gamma, const float* __restrict__ bn_beta,
    const float* __restrict__ bn_mean, const float* __restrict__ bn_var,
    const float* __restrict__ fc_w, const float* __restrict__ fc_b,
    const float* __restrict__ reg_w, const float* __restrict__ reg_b,
    float* __restrict__ out)
{
    extern __shared__ float sm[];
    const int tid = threadIdx.x;
    const int blk = blockIdx.x;
    const float4* packW = g_pack;
    const bool dotw = (tid < 480);

    /* ============ g3 wavefront: blocks 0..79 (cluster of 8 = time group) === */
    if (blk < 80) {
        const int t = blk >> 3;
        const int c = blk & 7;
        const int q  = tid >> 3;          /* 0..59  row within CTA slice */
        const int qk = tid & 7;           /* 0..7   k-eighth (20 elems)  */
        const int jrow = dotw ? ((q / HSS) * H + c * HSS + (q % HSS)) : 0;

        const uint32_t mb = smem_u32(sm);  /* mbarrier, 8 bytes */
        float* xin2 = sm + 4;              /* [2][H] (16B aligned) */
        float* hbuf = xin2 + 2 * H;        /* [2][H] double-buffered h_prev */
        float* xps  = hbuf + 2 * H;        /* [RPC]  */
        float* hps  = xps + RPC;           /* [RPC]  */
        const uint32_t xin_base = smem_u32(xin2);

        if (tid == 0) mbar_init(mb, 41);   /* 8 CTAs * 5 pushers + 1 warp15 */
        if (tid < 2 * H) hbuf[tid] = 0.f;
        __syncthreads();
        CLUSTER_SYNC();                    /* mbars visible cluster-wide */

        ull Wx[10], Wh[10];
        float bih_c = 0.f, bhh_c = 0.f;
        if (dotw) {   /* preload wih(0), whh(0), biases(0) */
            size_t bx = (size_t)(0 * 8 + c) * 2400 + tid;
            size_t bh = (size_t)(1280 + 0 * 8 + c) * 2400 + tid;
#pragma unroll
            for (int i4 = 0; i4 < 5; ++i4) {
                float4 f = __ldg(&packW[bx + i4 * 480]);
                Wx[2 * i4] = pack2(f.x, f.y); Wx[2 * i4 + 1] = pack2(f.z, f.w);
                float4 g = __ldg(&packW[bh + i4 * 480]);
                Wh[2 * i4] = pack2(g.x, g.y); Wh[2 * i4 + 1] = pack2(g.z, g.w);
            }
            if (qk == 0) { bih_c = __ldg(&g3_bih[jrow]); bhh_c = __ldg(&g3_bhh[jrow]); }
        }

        /* initial staging: xin[0] from branch; hbuf[0] = S(1,t-1) */
        if (tid == 0) poll_ge(&g_flags[DONE_IDX(0, t)], FULL);
        if (t > 0 && tid == 480) poll_ge(&g_flags[DONE_IDX(1, t - 1)], FULL);
        __syncthreads();
        if (tid < 40)
            *(float4*)&xin2[tid * 4] = __ldcg((const float4*)&g_S[t * H + tid * 4]);
        if (t > 0 && !dotw) {
            const int lane = tid - 480;
            const float4* src = (const float4*)&g_S[((size_t)1 * NCH + (t - 1)) * H];
            ((float4*)hbuf)[lane] = __ldcg(src + lane);
            if (lane < 8) ((float4*)hbuf)[32 + lane] = __ldcg(src + 32 + lane);
        }
        __syncthreads();

        for (int l = 0; l < NL; ++l) {
            const int cur = l & 1, nxt = cur ^ 1;

            if (dotw) {
                /* fused X + H dots */
                const float* xv  = xin2 + cur * H + qk * HSS;
                const float* hv0 = hbuf + cur * H + qk * HSS;
                ull a0 = 0, a1 = 0, b0 = 0, b1 = 0;
#pragma unroll
                for (int i4 = 0; i4 < 5; ++i4) {
                    ulonglong2 xh = *(const ulonglong2*)(xv + i4 * 4);
                    ulonglong2 hh = *(const ulonglong2*)(hv0 + i4 * 4);
                    fma2(a0, Wx[2 * i4], xh.x); fma2(a1, Wx[2 * i4 + 1], xh.y);
                    fma2(b0, Wh[2 * i4], hh.x); fma2(b1, Wh[2 * i4 + 1], hh.y);
                }
                float ax = upsum(a0, a1);
                float ah = upsum(b0, b1);
                ax += __shfl_xor_sync(0xffffffffu, ax, 1);
                ah += __shfl_xor_sync(0xffffffffu, ah, 1);
                ax += __shfl_xor_sync(0xffffffffu, ax, 2);
                ah += __shfl_xor_sync(0xffffffffu, ah, 2);
                ax += __shfl_xor_sync(0xffffffffu, ax, 4);
                ah += __shfl_xor_sync(0xffffffffu, ah, 4);
                if (qk == 0) { xps[q] = ax + bih_c; hps[q] = ah + bhh_c; }
                BAR_DOT();                       /* dots -> gate (480 threads) */

                if (tid < 32) {                  /* warp 0: gate + push */
                    if (tid < HSS) {
                        const int i = tid;
                        float hp_i = hbuf[cur * H + c * HSS + i];
                        float r = sigm(xps[i]            + hps[i]);
                        float z = sigm(xps[HSS + i]      + hps[HSS + i]);
                        float n = tanh_f(xps[2*HSS + i]  + r * hps[2*HSS + i]);
                        float hn = (1.f - z) * n + z * hp_i;
                        xin2[nxt * H + c * HSS + i] = hn;   /* local slice */
                        __stcg(&g_S[((size_t)(l + 1) * NCH + t) * H + c * HSS + i], hn);
                        red_release(&g_flags[DONE_IDX(l + 1, t)], 1);
                    }
                    __syncwarp();
                    if (tid < 5) {               /* 5 pushers: vector bcast */
                        float4 v = *(float4*)&xin2[nxt * H + c * HSS + tid * 4];
                        uint32_t a3 = xin_base +
                            (uint32_t)(nxt * H + c * HSS + tid * 4) * 4u;
#pragma unroll
                        for (int r2 = 0; r2 < 8; ++r2) {
                            if (r2 != c) st_cluster_f32x4(a3, r2, v);
                        }
#pragma unroll
                        for (int r2 = 0; r2 < 8; ++r2) mbar_arrive_rank(mb, r2);
                    }
                }
                /* prefetch weights + biases for l+1 before the wait */
                if (l + 1 < NL) {
                    size_t bx = (size_t)((l + 1) * 8 + c) * 2400 + tid;
                    size_t bh = (size_t)(1280 + (l + 1) * 8 + c) * 2400 + tid;
#pragma unroll
                    for (int i4 = 0; i4 < 5; ++i4) {
                        float4 f = __ldg(&packW[bx + i4 * 480]);
                        Wx[2 * i4] = pack2(f.x, f.y); Wx[2 * i4 + 1] = pack2(f.z, f.w);
                        float4 g = __ldg(&packW[bh + i4 * 480]);
                        Wh[2 * i4] = pack2(g.x, g.y); Wh[2 * i4 + 1] = pack2(g.z, g.w);
                    }
                    if (qk == 0) {
                        bih_c = __ldg(&g3_bih[(l + 1) * H3 + jrow]);
                        bhh_c = __ldg(&g3_bhh[(l + 1) * H3 + jrow]);
                    }
                }
                mbar_wait(mb, l & 1);
            } else {
                /* warp15: prefetch h for layer l+1 into hbuf[nxt] */
                if (t > 0 && l + 2 <= NL) {
                    if (tid == 480) poll_ge(&g_flags[DONE_IDX(l + 2, t - 1)], FULL);
                    __syncwarp();
                    const int lane = tid - 480;
                    const float4* src =
                        (const float4*)&g_S[((size_t)(l + 2) * NCH + (t - 1)) * H];
                    ((float4*)(hbuf + nxt * H))[lane] = __ldcg(src + lane);
                    if (lane < 8)
                        ((float4*)(hbuf + nxt * H))[32 + lane] = __ldcg(src + 32 + lane);
                    __syncwarp();
                }
                if (tid == 480) mbar_arrive_local(mb);
                mbar_wait(mb, l & 1);
            }
        }
        return;
    }

    /* ============ global GRU: blocks 80..87, one cluster, 8-way (R10) ====== */
    if (blk < 88) {
        const int c = blk - 80;

        float* xp_s  = sm;                       /* [CC*RPC] 48KB */
        float* bhh_s = xp_s + CC * RPC;          /* [RPC]    */
        float* h2    = bhh_s + RPC;              /* [2][H]   */
        float* hpb   = h2 + 2 * H;               /* [RPC]    */
        const uint32_t h2_base = smem_u32(h2);

        const int q2 = tid >> 3;
        const int qk = tid & 7;
        const int j  = dotw ? ((q2 / HSS) * H + c * HSS + (q2 % HSS)) : 0;

        ull W[10];
        if (dotw) {
            const float4* wr = (const float4*)&gw_hh[(size_t)j * H + qk * HSS];
#pragma unroll
            for (int i4 = 0; i4 < 5; ++i4) {
                float4 f = __ldg(wr + i4);
                W[2 * i4] = pack2(f.x, f.y); W[2 * i4 + 1] = pack2(f.z, f.w);
            }
        }
        for (int idx = tid; idx < CC * RPC; idx += NT) {
            int s = idx / RPC, qq = idx - s * RPC;
            int jj = (qq / HSS) * H + c * HSS + (qq % HSS);
            xp_s[idx] = x[s] * gw_ih[jj] + gb_ih[jj];
        }
        if (tid < RPC) {
            int jj = (tid / HSS) * H + c * HSS + (tid % HSS);
            bhh_s[tid] = gb_hh[jj];
        }
        if (tid < 2 * H) h2[tid] = 0.f;
        __syncthreads();
        CLUSTER_SYNC();

        float hsum = 0.f;
        for (int s = 0; s < CC; ++s) {
            const int cur = s & 1, nxt = cur ^ 1;
            if (dotw) {
                const float* hv0 = h2 + cur * H + qk * HSS;
                ull a0 = 0, a1 = 0;
#pragma unroll
                for (int i4 = 0; i4 < 5; ++i4) {
                    ulonglong2 hv = *(const ulonglong2*)(hv0 + i4 * 4);
                    fma2(a0, W[2 * i4], hv.x);
                    fma2(a1, W[2 * i4 + 1], hv.y);
                }
                float a = upsum(a0, a1);
                a += __shfl_xor_sync(0xffffffffu, a, 1);
                a += __shfl_xor_sync(0xffffffffu, a, 2);
                a += __shfl_xor_sync(0xffffffffu, a, 4);
                if (qk == 0) hpb[q2] = a + bhh_s[q2];
            }
            __syncthreads();
            if (tid < HSS) {
                const float* xpt = xp_s + s * RPC;
                const int i = tid;
                float r = sigm(xpt[i]            + hpb[i]);
                float z = sigm(xpt[HSS + i]      + hpb[HSS + i]);
                float n = tanh_f(xpt[2*HSS + i]  + r * hpb[2*HSS + i]);
                float hn = (1.f - z) * n + z * h2[cur * H + c * HSS + i];
                hsum += hn;
                uint32_t a2 = h2_base + (uint32_t)(nxt * H + c * HSS + i) * 4u;
#pragma unroll
                for (int r2 = 0; r2 < 8; ++r2) st_cluster_f32(a2, r2, hn);
            }
            CLUSTER_SYNC();
        }
        if (tid < HSS) {
            __stcg(&g_xl[c * HSS + tid], hsum * (1.f / CC));
            red_release(&g_flags[GDONE_IDX], 1);
        }
        return;
    }

    /* ============ branch GRUs: blocks 88..107 (2 CTAs/branch, 4 pairs/cluster) */
    if (blk < 108) {
        const int pairblk = blk - 88;
        const int b    = pairblk >> 1;
        const int hh   = pairblk & 1;
        const int rank = pairblk & 7;

        float* xp_s = sm;                      /* [TT*240]  */
        float* h2   = xp_s + TT * 240;         /* [2][H]    */
        float* hp_s = h2 + 2 * H;              /* [240]     */
        const uint32_t h2b = smem_u32(h2);

        const int qk2 = tid & 1;
        const int gi  = tid >> 1;
        const int g   = gi / 80;
        const int ip  = gi - g * 80;
        const int jrow = dotw ? (g * H + hh * 80 + ip) : 0;

        ull W[40];
        if (dotw) {
            size_t base = (size_t)G3_F4 + (size_t)(b * 2 + hh) * 9600 + tid;
#pragma unroll
            for (int i4 = 0; i4 < 20; ++i4) {
                float4 f = __ldg(&packW[base + i4 * 480]);
                W[2 * i4] = pack2(f.x, f.y); W[2 * i4 + 1] = pack2(f.z, f.w);
            }
        }
        float bhh_v = 0.f;
        if (dotw && qk2 == 0) bhh_v = __ldg(&b_bhh[b * H3 + jrow]);

        for (int idx = tid; idx < TT * 240; idx += NT) {
            int tt = idx / 240, lr = idx - tt * 240;
            int jj = (lr / 80) * H + hh * 80 + (lr % 80);
            xp_s[idx] = x[b * TT + tt] * b_wih[b * H3 + jj] + b_bih[b * H3 + jj];
        }
        if (tid < 2 * H) h2[tid] = 0.f;
        __syncthreads();
        CLUSTER_SYNC();                                    /* sync #1 */

        for (int tt = 0; tt < TT; ++tt) {
            const int cur = tt & 1, nxt = cur ^ 1;
            if (dotw) {
                const float* hv0 = h2 + cur * H + qk2 * 80;
                ull a0 = 0, a1 = 0;
#pragma unroll
                for (int i4 = 0; i4 < 20; ++i4) {
                    ulonglong2 hv = *(const ulonglong2*)(hv0 + i4 * 4);
                    fma2(a0, W[2 * i4], hv.x);
                    fma2(a1, W[2 * i4 + 1], hv.y);
                }
                float a = upsum(a0, a1);
                a += __shfl_xor_sync(0xffffffffu, a, 1);
                if (qk2 == 0) hp_s[g * 80 + ip] = a + bhh_v;
            }
            __syncthreads();

            if (dotw && qk2 == 0 && gi < 80) {
                const int i = gi;
                const float* xpt = xp_s + tt * 240;
                float r = sigm(xpt[i]          + hp_s[i]);
                float z = sigm(xpt[80 + i]     + hp_s[80 + i]);
                float n = tanh_f(xpt[160 + i]  + r * hp_s[160 + i]);
                float hn = (1.f - z) * n + z * h2[cur * H + hh * 80 + i];
                uint32_t a3 = h2b + (uint32_t)(nxt * H + hh * 80 + i) * 4u;
                st_cluster_f32(a3, rank, hn);
                st_cluster_f32(a3, rank ^ 1, hn);
            }
            CLUSTER_SYNC();                                /* syncs #2..#21 */
        }
        if (tid < 80) {
            __stcg(&g_S[b * H + hh * 80 + tid], h2[0 * H + hh * 80 + tid]);
            red_release(&g_flags[DONE_IDX(0, b)], 1);
        }
        CLUSTER_SYNC();                                    /* sync #22 */
        return;
    }

    /* ============ branch-cluster fillers: blocks 108..111 ================== */
    if (blk < 112) {
        for (int i = 0; i < TT + 2; ++i) CLUSTER_SYNC();   /* match 22 syncs */
        return;
    }

    /* ============ epilogue: block 112 (113..119 idle, no cluster ops) ====== */
    if (blk == 112) {
        if (tid == 0) {
            for (int tt = 0; tt < NCH; ++tt) poll_ge(&g_flags[DONE_IDX(NL, tt)], FULL);
            poll_ge(&g_flags[GDONE_IDX], FULL);
        }
        __syncthreads();

        float* xr = sm;
        if (tid < H) {
            float m = 0.f;
#pragma unroll
            for (int tt = 0; tt < NCH; ++tt) m += __ldcg(&g_S[(NL * NCH + tt) * H + tid]);
            m *= (1.f / NCH);
            m = fmaxf(m, 0.f);
            float xnew = __ldcg(&g_xl[tid]) * m;
            float xb = (xnew - bn_mean[tid]) * rsqrtf(bn_var[tid] + 1e-5f)
                       * bn_gamma[tid] + bn_beta[tid];
            xr[tid] = fmaxf(xb, 0.f);
        }
        __syncthreads();

        if (tid < NCLS + CC) {
            const float* wrow; float bias;
            if (tid < NCLS) { wrow = fc_w + tid * H;           bias = fc_b[tid]; }
            else            { wrow = reg_w + (tid - NCLS) * H; bias = reg_b[tid - NCLS]; }
            float a = bias;
#pragma unroll 10
            for (int k = 0; k < H; ++k) a += wrow[k] * xr[k];
            out[tid] = a;
        }
        return;
    }
}

extern "C" void kernel_launch(void* const* d_in, const int* in_sizes, int n_in,
                              void* d_out, int out_size) {
    const float* x        = (const float*)d_in[0];
    const float* b_wih    = (const float*)d_in[1];
    const float* b_whh    = (const float*)d_in[2];
    const float* b_bih    = (const float*)d_in[3];
    const float* b_bhh    = (const float*)d_in[4];
    const float* gw_ih    = (const float*)d_in[5];
    const float* gw_hh    = (const float*)d_in[6];
    const float* gb_ih    = (const float*)d_in[7];
    const float* gb_hh    = (const float*)d_in[8];
    const float* g3_wih   = (const float*)d_in[9];
    const float* g3_whh   = (const float*)d_in[10];
    const float* g3_bih   = (const float*)d_in[11];
    const float* g3_bhh   = (const float*)d_in[12];
    const float* bn_gamma = (const float*)d_in[13];
    const float* bn_beta  = (const float*)d_in[14];
    const float* bn_mean  = (const float*)d_in[15];
    const float* bn_var   = (const float*)d_in[16];
    const float* fc_w     = (const float*)d_in[17];
    const float* fc_b     = (const float*)d_in[18];
    const float* reg_w    = (const float*)d_in[19];
    const float* reg_b    = (const float*)d_in[20];
    float* out = (float*)d_out;

    /* max role smem: global GRU = CC*RPC + RPC + 2H + RPC floats (~50KB) */
    const int smem_bytes = (CC * RPC + RPC + 2 * H + RPC) * (int)sizeof(float);
    cudaFuncSetAttribute(spectral_kernel,
                         cudaFuncAttributeMaxDynamicSharedMemorySize, smem_bytes);

    pack_kernel<<<(PACK_F4 + 255) / 256, 256>>>(
        (const float4*)g3_wih, (const float4*)g3_whh, (const float4*)b_whh);
    spectral_kernel<<<NBLK, NT, smem_bytes>>>(
        x, b_wih, b_bih, b_bhh,
        gw_ih, gw_hh, gb_ih, gb_hh,
        g3_bih, g3_bhh,
        bn_gamma, bn_beta, bn_mean, bn_var,
        fc_w, fc_b, reg_w, reg_b, out);
}

// round 14
// speedup vs baseline: 1.3000x; 1.2937x over previous
#include <cuda_runtime.h>
#include <math.h>
#include <stdint.h>

#define H    160
#define H3   480
#define CC   200
#define TT   20
#define NCH  10
#define NL   160
#define NCLS 16
#define NT   352
#define NDOT 320
#define NBLK 96
#define FULL 160

#define NFLAGS ((NL + 1) * NCH + 1)
#define GDONE_IDX ((NL + 1) * NCH)
#define DONE_IDX(l, t) ((l) * NCH + (t))

/* pack: g3 chunks [(m*NL+l)*8+c] m=0 wih / 1 whh, then branch chunks [b*8+c] */
#define G3_CHUNKS (2 * NL * 8)          /* 2560 */
#define BR_CHUNKS (NCH * 8)             /* 80   */
#define CHUNK_F4  3200                  /* 10 i4 x 320 tid */
#define PACK_F4   ((G3_CHUNKS + BR_CHUNKS) * CHUNK_F4)

__device__ float4 g_pack[PACK_F4];          /* ~135 MB */
__device__ float  g_S[(NL + 1) * NCH * H];
__device__ float  g_xl[H];
__device__ int    g_flags[NFLAGS];

typedef unsigned long long ull;

__device__ __forceinline__ float sigm(float v)   { return __fdividef(1.f, 1.f + __expf(-v)); }
__device__ __forceinline__ float tanh_f(float v) { return __fdividef(2.f, 1.f + __expf(-2.f * v)) - 1.f; }

__device__ __forceinline__ void poll_ge(const int* f, int tgt) {
    int v;
    do {
        asm volatile("ld.acquire.gpu.s32 %0, [%1];" : "=r"(v) : "l"(f) : "memory");
    } while (v < tgt);
}
__device__ __forceinline__ void red_release(int* f, int val) {
    asm volatile("red.release.gpu.add.s32 [%0], %1;" :: "l"(f), "r"(val) : "memory");
}
__device__ __forceinline__ uint32_t smem_u32(const void* p) {
    uint32_t a;
    asm("{ .reg .u64 t; cvta.to.shared.u64 t, %1; cvt.u32.u64 %0, t; }" : "=r"(a) : "l"(p));
    return a;
}
__device__ __forceinline__ void st_cluster_f32(uint32_t laddr, int rank, float v) {
    uint32_t r;
    asm("mapa.shared::cluster.u32 %0, %1, %2;" : "=r"(r) : "r"(laddr), "r"(rank));
    asm volatile("st.shared::cluster.f32 [%0], %1;" :: "r"(r), "f"(v) : "memory");
}
#define CLUSTER_SYNC() do { \
    asm volatile("barrier.cluster.arrive.aligned;" ::: "memory"); \
    asm volatile("barrier.cluster.wait.aligned;"   ::: "memory"); } while (0)
#define CLUSTER_ARRIVE() asm volatile("barrier.cluster.arrive;" ::: "memory")
#define CLUSTER_WAIT()   asm volatile("barrier.cluster.wait;"   ::: "memory")

__device__ __forceinline__ ull pack2(float x, float y) {
    ull u; asm("mov.b64 %0, {%1, %2};" : "=l"(u) : "f"(x), "f"(y)); return u;
}
__device__ __forceinline__ void fma2(ull& acc, ull a, ull b) {
    asm("fma.rn.f32x2 %0, %1, %2, %0;" : "+l"(acc) : "l"(a), "l"(b));
}
__device__ __forceinline__ float upsum(ull a0, ull a1) {
    float l0, h0, l1, h1;
    asm("mov.b64 {%0, %1}, %2;" : "=f"(l0), "=f"(h0) : "l"(a0));
    asm("mov.b64 {%0, %1}, %2;" : "=f"(l1), "=f"(h1) : "l"(a1));
    return (l0 + h0) + (l1 + h1);
}

/* ---------- pack kernel (also zeroes flags) ---------- */
__global__ void pack_kernel(const float4* __restrict__ wih,
                            const float4* __restrict__ whh,
                            const float4* __restrict__ bwhh) {
    int id = blockIdx.x * blockDim.x + threadIdx.x;
    if (id < NFLAGS) g_flags[id] = 0;
    if (id >= PACK_F4) return;
    int chunk  = id / CHUNK_F4;
    int within = id - chunk * CHUNK_F4;
    int i4  = within / 320;
    int tid = within - i4 * 320;
    int qk = tid & 3, qp = tid >> 2;
    int t20 = qp >> 2, mm = qp & 3;
    float4 v = make_float4(0.f, 0.f, 0.f, 0.f);
    if (mm < 3) {
        if (chunk < G3_CHUNKS) {
            int c = chunk & 7, lm = chunk >> 3;
            int l = lm % NL, m = lm / NL;
            int jrow = mm * H + c * 20 + t20;
            const float4* src = (m == 0) ? wih : whh;
            v = src[((size_t)l * H3 + jrow) * 40 + qk * 10 + i4];
        } else {
            int cb = chunk - G3_CHUNKS;
            int c = cb & 7, b = cb >> 3;
            int jrow = mm * H + c * 20 + t20;
            v = bwhh[((size_t)b * H3 + jrow) * 40 + qk * 10 + i4];
        }
    }
    g_pack[id] = v;
}

/* ---------- main persistent kernel ---------- */
__global__ void __launch_bounds__(NT, 1) __cluster_dims__(8, 1, 1)
spectral_kernel(
    const float* __restrict__ x,
    const float* __restrict__ b_wih, const float* __restrict__ b_bih,
    const float* __restrict__ b_bhh,
    const float* __restrict__ gw_ih, const float* __restrict__ gw_hh,
    const float* __restrict__ gb_ih, const float* __restrict__ gb_hh,
    const float* __restrict__ g3_bih, const float* __restrict__ g3_bhh,
    const float* __restrict__ bn_gamma, const float* __restrict__ bn_beta,
    const float* __restrict__ bn_mean, const float* __restrict__ bn_var,
    const float* __restrict__ fc_w, const float* __restrict__ fc_b,
    const float* __restrict__ reg_w, const float* __restrict__ reg_b,
    float* __restrict__ out)
{
    extern __shared__ float sm[];
    const int tid = threadIdx.x;
    const int blk = blockIdx.x;
    const bool dotw  = (tid < NDOT);
    const int  qk  = tid & 3;
    const int  qp  = tid >> 2;
    const int  t20 = qp >> 2;       /* output index 0..19 */
    const int  mm  = qp & 3;        /* gate-row 0..2 (3 = pad) */
    const bool gatel = dotw && ((tid & 15) == 0);
    const int  gout  = tid >> 4;    /* 0..19 on gate lanes */
    const int  lb    = (tid & 31) & 16;

    /* ============ g3 wavefront + fused branch: blocks 0..79 ================ */
    if (blk < 80) {
        const int t = blk >> 3;
        const int c = blk & 7;

        float* xin2 = sm;                  /* [2][H] */
        float* hbuf = sm + 2 * H;          /* [2][H] */
        float* xs   = sm + 4 * H;          /* [TT]   */
        const uint32_t xin_base  = smem_u32(xin2);
        const uint32_t hbuf_base = smem_u32(hbuf);

        if (tid < 2 * H) { xin2[tid] = 0.f; hbuf[tid] = 0.f; }
        if (tid < TT) xs[tid] = __ldg(&x[t * TT + tid]);
        __syncthreads();
        CLUSTER_SYNC();                                           /* sync #1 */

        ull Wx[20], Wh[20];
        float wih3[3], bih3[3], bhh3[3];

        if (dotw) {
            /* Wh <- branch whh(t) slice; Wx <- g3 wih(0) slice */
            size_t bb = (size_t)(G3_CHUNKS + t * 8 + c) * CHUNK_F4 + tid;
            size_t bx = (size_t)((0 * NL + 0) * 8 + c) * CHUNK_F4 + tid;
#pragma unroll
            for (int i4 = 0; i4 < 10; ++i4) {
                float4 f = __ldg(&g_pack[bb + i4 * 320]);
                Wh[2 * i4] = pack2(f.x, f.y); Wh[2 * i4 + 1] = pack2(f.z, f.w);
                float4 g = __ldg(&g_pack[bx + i4 * 320]);
                Wx[2 * i4] = pack2(g.x, g.y); Wx[2 * i4 + 1] = pack2(g.z, g.w);
            }
        }
        if (gatel) {
#pragma unroll
            for (int g = 0; g < 3; ++g) {
                int j = g * H + c * 20 + gout;
                wih3[g] = __ldg(&b_wih[t * H3 + j]);
                bih3[g] = __ldg(&b_bih[t * H3 + j]);
                bhh3[g] = __ldg(&b_bhh[t * H3 + j]);
            }
        }

        /* ---- branch prologue: 20 GRU steps, input scalar xs[s] ---- */
        for (int s = 0; s < TT; ++s) {
            const int cur = s & 1, nxt = cur ^ 1;
            if (dotw) {
                const float* hv = hbuf + cur * H + qk * 40;
                ull b0 = 0, b1 = 0;
#pragma unroll
                for (int i4 = 0; i4 < 10; ++i4) {
                    ulonglong2 hh = *(const ulonglong2*)(hv + i4 * 4);
                    fma2(b0, Wh[2 * i4], hh.x);
                    fma2(b1, Wh[2 * i4 + 1], hh.y);
                }
                float ah = upsum(b0, b1);
                ah += __shfl_xor_sync(0xffffffffu, ah, 1);
                ah += __shfl_xor_sync(0xffffffffu, ah, 2);
                float ah1 = __shfl_sync(0xffffffffu, ah, lb + 4);
                float ah2 = __shfl_sync(0xffffffffu, ah, lb + 8);
                if (gatel) {
                    float xt = xs[s];
                    float r = sigm(wih3[0] * xt + bih3[0] + ah  + bhh3[0]);
                    float z = sigm(wih3[1] * xt + bih3[1] + ah1 + bhh3[1]);
                    float n = tanh_f(wih3[2] * xt + bih3[2] + r * (ah2 + bhh3[2]));
                    float hp = hbuf[cur * H + c * 20 + gout];
                    float hnew = (1.f - z) * n + z * hp;
                    uint32_t a3 = (s == TT - 1)
                        ? xin_base  + (uint32_t)(c * 20 + gout) * 4u
                        : hbuf_base + (uint32_t)(nxt * H + c * 20 + gout) * 4u;
#pragma unroll
                    for (int r2 = 0; r2 < 8; ++r2) st_cluster_f32(a3, r2, hnew);
                }
            }
            CLUSTER_SYNC();                              /* syncs #2..#21 */
        }

        /* ---- inter-phase: load g3 whh(0)+biases(0); stage/zero hbuf ---- */
        if (dotw) {
            size_t bh = (size_t)((1 * NL + 0) * 8 + c) * CHUNK_F4 + tid;
#pragma unroll
            for (int i4 = 0; i4 < 10; ++i4) {
                float4 g = __ldg(&g_pack[bh + i4 * 320]);
                Wh[2 * i4] = pack2(g.x, g.y); Wh[2 * i4 + 1] = pack2(g.z, g.w);
            }
        }
        if (gatel) {
#pragma unroll
            for (int g = 0; g < 3; ++g) {
                int j = g * H + c * 20 + gout;
                bih3[g] = __ldg(&g3_bih[j]);
                bhh3[g] = __ldg(&g3_bhh[j]);
            }
        }
        if (!dotw) {
            const int lane = tid - NDOT;
            if (t == 0) {
#pragma unroll
                for (int i = 0; i < 10; ++i) hbuf[lane + i * 32] = 0.f;
            } else {
                if (lane == 0) poll_ge(&g_flags[DONE_IDX(1, t - 1)], FULL);
                __syncwarp();
                const float4* src = (const float4*)&g_S[((size_t)1 * NCH + (t - 1)) * H];
                ((float4*)hbuf)[lane] = __ldcg(src + lane);
                if (lane < 8) ((float4*)hbuf)[32 + lane] = __ldcg(src + 32 + lane);
            }
        }
        CLUSTER_SYNC();                                  /* sync #22 */

        /* ---- g3 main loop: 160 layers ---- */
        for (int l = 0; l < NL; ++l) {
            const int cur = l & 1, nxt = cur ^ 1;
            if (dotw) {
                const float* xv = xin2 + cur * H + qk * 40;
                const float* hv = hbuf + cur * H + qk * 40;
                ull a0 = 0, a1 = 0, b0 = 0, b1 = 0;
#pragma unroll
                for (int i4 = 0; i4 < 10; ++i4) {
                    ulonglong2 xh = *(const ulonglong2*)(xv + i4 * 4);
                    ulonglong2 hh = *(const ulonglong2*)(hv + i4 * 4);
                    fma2(a0, Wx[2 * i4], xh.x); fma2(a1, Wx[2 * i4 + 1], xh.y);
                    fma2(b0, Wh[2 * i4], hh.x); fma2(b1, Wh[2 * i4 + 1], hh.y);
                }
                float ax = upsum(a0, a1), ah = upsum(b0, b1);
                ax += __shfl_xor_sync(0xffffffffu, ax, 1);
                ah += __shfl_xor_sync(0xffffffffu, ah, 1);
                ax += __shfl_xor_sync(0xffffffffu, ax, 2);
                ah += __shfl_xor_sync(0xffffffffu, ah, 2);
                float ax1 = __shfl_sync(0xffffffffu, ax, lb + 4);
                float ah1 = __shfl_sync(0xffffffffu, ah, lb + 4);
                float ax2 = __shfl_sync(0xffffffffu, ax, lb + 8);
                float ah2 = __shfl_sync(0xffffffffu, ah, lb + 8);
                if (gatel) {
                    float r = sigm(ax  + bih3[0] + ah  + bhh3[0]);
                    float z = sigm(ax1 + bih3[1] + ah1 + bhh3[1]);
                    float n = tanh_f(ax2 + bih3[2] + r * (ah2 + bhh3[2]));
                    float hp = hbuf[cur * H + c * 20 + gout];
                    float hnew = (1.f - z) * n + z * hp;
                    __stcg(&g_S[((size_t)(l + 1) * NCH + t) * H + c * 20 + gout], hnew);
                    red_release(&g_flags[DONE_IDX(l + 1, t)], 1);
                    uint32_t a3 = xin_base + (uint32_t)(nxt * H + c * 20 + gout) * 4u;
#pragma unroll
                    for (int r2 = 0; r2 < 8; ++r2) st_cluster_f32(a3, r2, hnew);
                }
            } else {
                if (t > 0 && l + 2 <= NL) {
                    const int lane = tid - NDOT;
                    if (lane == 0) poll_ge(&g_flags[DONE_IDX(l + 2, t - 1)], FULL);
                    __syncwarp();
                    const float4* src =
                        (const float4*)&g_S[((size_t)(l + 2) * NCH + (t - 1)) * H];
                    ((float4*)(hbuf + nxt * H))[lane] = __ldcg(src + lane);
                    if (lane < 8)
                        ((float4*)(hbuf + nxt * H))[32 + lane] = __ldcg(src + 32 + lane);
                }
            }
            CLUSTER_ARRIVE();
            if (dotw && l + 1 < NL) {
                size_t bx = (size_t)((0 * NL + (l + 1)) * 8 + c) * CHUNK_F4 + tid;
                size_t bh = (size_t)((1 * NL + (l + 1)) * 8 + c) * CHUNK_F4 + tid;
#pragma unroll
                for (int i4 = 0; i4 < 10; ++i4) {
                    float4 f = __ldg(&g_pack[bx + i4 * 320]);
                    Wx[2 * i4] = pack2(f.x, f.y); Wx[2 * i4 + 1] = pack2(f.z, f.w);
                    float4 g = __ldg(&g_pack[bh + i4 * 320]);
                    Wh[2 * i4] = pack2(g.x, g.y); Wh[2 * i4 + 1] = pack2(g.z, g.w);
                }
                if (gatel) {
#pragma unroll
                    for (int g = 0; g < 3; ++g) {
                        int j = g * H + c * 20 + gout;
                        bih3[g] = __ldg(&g3_bih[(l + 1) * H3 + j]);
                        bhh3[g] = __ldg(&g3_bhh[(l + 1) * H3 + j]);
                    }
                }
            }
            CLUSTER_WAIT();                              /* syncs #23..#182 */
        }
        return;
    }

    /* ============ global GRU: blocks 80..87, same cell, 200 steps ========== */
    if (blk < 88) {
        const int c = blk - 80;

        float* xin2 = sm;                  /* unused buffer space */
        float* hbuf = sm + 2 * H;          /* [2][H] */
        float* xs   = sm + 4 * H;          /* [CC]   */
        const uint32_t hbuf_base = smem_u32(hbuf);
        (void)xin2;

        if (tid < 2 * H) hbuf[tid] = 0.f;
        if (tid < CC) xs[tid] = __ldg(&x[tid]);
        __syncthreads();
        CLUSTER_SYNC();                                  /* sync #1 */

        ull Wh[20];
        float wih3[3], bih3[3], bhh3[3];
        if (dotw) {
            if (mm < 3) {
                int jrow = mm * H + c * 20 + t20;
                const float4* wr = (const float4*)gw_hh + (size_t)jrow * 40 + qk * 10;
#pragma unroll
                for (int i4 = 0; i4 < 10; ++i4) {
                    float4 f = __ldg(wr + i4);
                    Wh[2 * i4] = pack2(f.x, f.y); Wh[2 * i4 + 1] = pack2(f.z, f.w);
                }
            } else {
#pragma unroll
                for (int i = 0; i < 20; ++i) Wh[i] = 0ull;
            }
        }
        if (gatel) {
#pragma unroll
            for (int g = 0; g < 3; ++g) {
                int j = g * H + c * 20 + gout;
                wih3[g] = __ldg(&gw_ih[j]);
                bih3[g] = __ldg(&gb_ih[j]);
                bhh3[g] = __ldg(&gb_hh[j]);
            }
        }

        float hsum = 0.f;
        for (int s = 0; s < CC; ++s) {
            const int cur = s & 1, nxt = cur ^ 1;
            if (dotw) {
                const float* hv = hbuf + cur * H + qk * 40;
                ull b0 = 0, b1 = 0;
#pragma unroll
                for (int i4 = 0; i4 < 10; ++i4) {
                    ulonglong2 hh = *(const ulonglong2*)(hv + i4 * 4);
                    fma2(b0, Wh[2 * i4], hh.x);
                    fma2(b1, Wh[2 * i4 + 1], hh.y);
                }
                float ah = upsum(b0, b1);
                ah += __shfl_xor_sync(0xffffffffu, ah, 1);
                ah += __shfl_xor_sync(0xffffffffu, ah, 2);
                float ah1 = __shfl_sync(0xffffffffu, ah, lb + 4);
                float ah2 = __shfl_sync(0xffffffffu, ah, lb + 8);
                if (gatel) {
                    float xt = xs[s];
                    float r = sigm(wih3[0] * xt + bih3[0] + ah  + bhh3[0]);
                    float z = sigm(wih3[1] * xt + bih3[1] + ah1 + bhh3[1]);
                    float n = tanh_f(wih3[2] * xt + bih3[2] + r * (ah2 + bhh3[2]));
                    float hp = hbuf[cur * H + c * 20 + gout];
                    float hnew = (1.f - z) * n + z * hp;
                    hsum += hnew;
                    uint32_t a3 = hbuf_base + (uint32_t)(nxt * H + c * 20 + gout) * 4u;
#pragma unroll
                    for (int r2 = 0; r2 < 8; ++r2) st_cluster_f32(a3, r2, hnew);
                }
            }
            CLUSTER_SYNC();                              /* syncs #2..#201 */
        }
        if (gatel) {
            __stcg(&g_xl[c * 20 + gout], hsum * (1.f / CC));
            red_release(&g_flags[GDONE_IDX], 1);
        }
        return;
    }

    /* ============ epilogue: block 88 (89..95 idle; cluster 11 never syncs) = */
    if (blk == 88) {
        if (tid == 0) {
            for (int tt = 0; tt < NCH; ++tt) poll_ge(&g_flags[DONE_IDX(NL, tt)], FULL);
            poll_ge(&g_flags[GDONE_IDX], FULL);
        }
        __syncthreads();

        float* xr = sm;
        if (tid < H) {
            float m = 0.f;
#pragma unroll
            for (int tt = 0; tt < NCH; ++tt) m += __ldcg(&g_S[(NL * NCH + tt) * H + tid]);
            m *= (1.f / NCH);
            m = fmaxf(m, 0.f);
            float xnew = __ldcg(&g_xl[tid]) * m;
            float xb = (xnew - bn_mean[tid]) * rsqrtf(bn_var[tid] + 1e-5f)
                       * bn_gamma[tid] + bn_beta[tid];
            xr[tid] = fmaxf(xb, 0.f);
        }
        __syncthreads();

        if (tid < NCLS + CC) {
            const float* wrow; float bias;
            if (tid < NCLS) { wrow = fc_w + tid * H;           bias = fc_b[tid]; }
            else            { wrow = reg_w + (tid - NCLS) * H; bias = reg_b[tid - NCLS]; }
            float a = bias;
#pragma unroll 10
            for (int k = 0; k < H; ++k) a += wrow[k] * xr[k];
            out[tid] = a;
        }
        return;
    }
}

extern "C" void kernel_launch(void* const* d_in, const int* in_sizes, int n_in,
                              void* d_out, int out_size) {
    const float* x        = (const float*)d_in[0];
    const float* b_wih    = (const float*)d_in[1];
    const float* b_whh    = (const float*)d_in[2];
    const float* b_bih    = (const float*)d_in[3];
    const float* b_bhh    = (const float*)d_in[4];
    const float* gw_ih    = (const float*)d_in[5];
    const float* gw_hh    = (const float*)d_in[6];
    const float* gb_ih    = (const float*)d_in[7];
    const float* gb_hh    = (const float*)d_in[8];
    const float* g3_wih   = (const float*)d_in[9];
    const float* g3_whh   = (const float*)d_in[10];
    const float* g3_bih   = (const float*)d_in[11];
    const float* g3_bhh   = (const float*)d_in[12];
    const float* bn_gamma = (const float*)d_in[13];
    const float* bn_beta  = (const float*)d_in[14];
    const float* bn_mean  = (const float*)d_in[15];
    const float* bn_var   = (const float*)d_in[16];
    const float* fc_w     = (const float*)d_in[17];
    const float* fc_b     = (const float*)d_in[18];
    const float* reg_w    = (const float*)d_in[19];
    const float* reg_b    = (const float*)d_in[20];
    float* out = (float*)d_out;

    const int smem_bytes = (4 * H + CC + 16) * (int)sizeof(float);

    pack_kernel<<<(PACK_F4 + 255) / 256, 256>>>(
        (const float4*)g3_wih, (const float4*)g3_whh, (const float4*)b_whh);
    spectral_kernel<<<NBLK, NT, smem_bytes>>>(
        x, b_wih, b_bih, b_bhh,
        gw_ih, gw_hh, gb_ih, gb_hh,
        g3_bih, g3_bhh,
        bn_gamma, bn_beta, bn_mean, bn_var,
        fc_w, fc_b, reg_w, reg_b, out);
}

// round 15
// speedup vs baseline: 1.4858x; 1.1429x over previous
#include <cuda_runtime.h>
#include <cuda_fp16.h>
#include <math.h>
#include <stdint.h>

#define H    160
#define H3   480
#define CC   200
#define TT   20
#define NCH  10
#define NL   160
#define NCLS 16
#define HSS  20          /* h-slice per CTA (8-way split) */
#define RPC  60          /* rows per CTA = 3*HSS */
#define NT   512
#define NBLK 120
#define FULL 160

#define NFLAGS ((NL + 1) * NCH + 1)
#define GDONE_IDX ((NL + 1) * NCH)
#define DONE_IDX(l, t) ((l) * NCH + (t))

/* fp16 packed weights, uint2 = 4 halfs.
   g3 wih chunks [0,1280), g3 whh chunks [1280,2560), branch after.
   g3 chunk = 2400 uint2 (480 tid x 5 i4); branch chunk = 9600 (480 x 20). */
#define G3_U2   (2560 * 2400)
#define BR_U2   (20 * 9600)
#define PACK_U2 (G3_U2 + BR_U2)

__device__ uint2  g_pack[PACK_U2];          /* ~50.7 MB */
__device__ float  g_S[(NL + 1) * NCH * H];
__device__ float  g_xl[H];
__device__ int    g_flags[NFLAGS];

typedef unsigned long long ull;

__device__ __forceinline__ float sigm(float v)   { return __fdividef(1.f, 1.f + __expf(-v)); }
__device__ __forceinline__ float tanh_f(float v) { return __fdividef(2.f, 1.f + __expf(-2.f * v)) - 1.f; }

__device__ __forceinline__ void poll_ge(const int* f, int tgt) {
    int v;
    do {
        asm volatile("ld.acquire.gpu.s32 %0, [%1];" : "=r"(v) : "l"(f) : "memory");
    } while (v < tgt);
}
__device__ __forceinline__ void red_release(int* f, int val) {
    asm volatile("red.release.gpu.add.s32 [%0], %1;" :: "l"(f), "r"(val) : "memory");
}
__device__ __forceinline__ uint32_t smem_u32(const void* p) {
    uint32_t a;
    asm("{ .reg .u64 t; cvta.to.shared.u64 t, %1; cvt.u32.u64 %0, t; }" : "=r"(a) : "l"(p));
    return a;
}
__device__ __forceinline__ void st_cluster_f32(uint32_t laddr, int rank, float v) {
    uint32_t r;
    asm("mapa.shared::cluster.u32 %0, %1, %2;" : "=r"(r) : "r"(laddr), "r"(rank));
    asm volatile("st.shared::cluster.f32 [%0], %1;" :: "r"(r), "f"(v) : "memory");
}
__device__ __forceinline__ void st_cluster_f32x4(uint32_t laddr, int rank, float4 v) {
    uint32_t r;
    asm("mapa.shared::cluster.u32 %0, %1, %2;" : "=r"(r) : "r"(laddr), "r"(rank));
    asm volatile("st.shared::cluster.v4.f32 [%0], {%1, %2, %3, %4};"
                 :: "r"(r), "f"(v.x), "f"(v.y), "f"(v.z), "f"(v.w) : "memory");
}
#define CLUSTER_SYNC() do { \
    asm volatile("barrier.cluster.arrive.aligned;" ::: "memory"); \
    asm volatile("barrier.cluster.wait.aligned;"   ::: "memory"); } while (0)
#define CLUSTER_ARRIVE() asm volatile("barrier.cluster.arrive;" ::: "memory")
#define CLUSTER_WAIT()   asm volatile("barrier.cluster.wait;"   ::: "memory")
#define BAR_DOT()        asm volatile("bar.sync 1, 480;" ::: "memory")

__device__ __forceinline__ ull pack2(float x, float y) {
    ull u; asm("mov.b64 %0, {%1, %2};" : "=l"(u) : "f"(x), "f"(y)); return u;
}
__device__ __forceinline__ void fma2(ull& acc, ull a, ull b) {
    asm("fma.rn.f32x2 %0, %1, %2, %0;" : "+l"(acc) : "l"(a), "l"(b));
}
__device__ __forceinline__ float upsum(ull a0, ull a1) {
    float l0, h0, l1, h1;
    asm("mov.b64 {%0, %1}, %2;" : "=f"(l0), "=f"(h0) : "l"(a0));
    asm("mov.b64 {%0, %1}, %2;" : "=f"(l1), "=f"(h1) : "l"(a1));
    return (l0 + h0) + (l1 + h1);
}
__device__ __forceinline__ void h4_to_2ull(uint2 r, ull& a, ull& b) {
    __half2 h0, h1;
    *(uint32_t*)&h0 = r.x; *(uint32_t*)&h1 = r.y;
    float2 f0 = __half22float2(h0), f1 = __half22float2(h1);
    a = pack2(f0.x, f0.y); b = pack2(f1.x, f1.y);
}

/* ---------- pack kernel (fp16, also zeroes flags) ---------- */
__global__ void pack_kernel(const float* __restrict__ wih,
                            const float* __restrict__ whh,
                            const float* __restrict__ bwhh) {
    int id = blockIdx.x * blockDim.x + threadIdx.x;
    if (id < NFLAGS) g_flags[id] = 0;
    if (id >= PACK_U2) return;
    float4 f;
    if (id < G3_U2) {
        int chunkid = id / 2400;
        int within  = id - chunkid * 2400;
        int i4 = within / 480, tid = within - i4 * 480;
        int m  = chunkid / 1280;
        int lc = chunkid - m * 1280;
        int l = lc >> 3, c = lc & 7;
        int q = tid >> 3, qk = tid & 7;
        int jrow = (q / HSS) * H + c * HSS + (q % HSS);
        int k = qk * 20 + i4 * 4;
        const float* src = (m == 0) ? wih : whh;
        f = *(const float4*)(src + ((size_t)l * H3 + jrow) * H + k);
    } else {
        int id2    = id - G3_U2;
        int chunk  = id2 / 9600;
        int within = id2 - chunk * 9600;
        int i4 = within / 480, tid = within - i4 * 480;
        int b = chunk >> 1, hh = chunk & 1;
        int qk2 = tid & 1, gi = tid >> 1;
        int g = gi / 80, ip = gi - g * 80;
        int j = g * H + hh * 80 + ip;
        int k = qk2 * 80 + i4 * 4;
        f = *(const float4*)(bwhh + ((size_t)b * H3 + j) * H + k);
    }
    __half2 h01 = __floats2half2_rn(f.x, f.y);
    __half2 h23 = __floats2half2_rn(f.z, f.w);
    uint2 v;
    v.x = *(uint32_t*)&h01;
    v.y = *(uint32_t*)&h23;
    g_pack[id] = v;
}

/* ---------- main persistent kernel ---------- */
__global__ void __launch_bounds__(NT, 1) __cluster_dims__(8, 1, 1)
spectral_kernel(
    const float* __restrict__ x,
    const float* __restrict__ b_wih, const float* __restrict__ b_bih,
    const float* __restrict__ b_bhh,
    const float* __restrict__ gw_ih, const float* __restrict__ gw_hh,
    const float* __restrict__ gb_ih, const float* __restrict__ gb_hh,
    const float* __restrict__ g3_bih, const float* __restrict__ g3_bhh,
    const float* __restrict__ bn_gamma, const float* __restrict__ bn_beta,
    const float* __restrict__ bn_mean, const float* __restrict__ bn_var,
    const float* __restrict__ fc_w, const float* __restrict__ fc_b,
    const float* __restrict__ reg_w, const float* __restrict__ reg_b,
    float* __restrict__ out)
{
    extern __shared__ float sm[];
    const int tid = threadIdx.x;
    const int blk = blockIdx.x;
    const uint2* packW = g_pack;
    const bool dotw = (tid < 480);

    /* ============ g3 wavefront: blocks 0..79 (cluster of 8 = time group) === */
    if (blk < 80) {
        const int t = blk >> 3;
        const int c = blk & 7;
        const int q  = tid >> 3;          /* 0..59  row within CTA slice */
        const int qk = tid & 7;           /* 0..7   k-eighth (20 elems)  */
        const int jrow = dotw ? ((q / HSS) * H + c * HSS + (q % HSS)) : 0;

        float* xin2 = sm;                 /* [2][H] */
        float* hbuf = sm + 2 * H;         /* [2][H] double-buffered h_prev */
        float* xps  = sm + 4 * H;         /* [RPC]  */
        float* hps  = xps + RPC;          /* [RPC]  */
        const uint32_t xin_base = smem_u32(xin2);

        if (tid < 2 * H) hbuf[tid] = 0.f;
        CLUSTER_SYNC();   /* siblings alive + hbuf zeroed */

        ull Wx[10], Wh[10];
        float bih_c = 0.f, bhh_c = 0.f;
        if (dotw) {   /* preload wih(0), whh(0), biases(0) */
            size_t bx = (size_t)(0 * 8 + c) * 2400 + tid;
            size_t bh = (size_t)(1280 + 0 * 8 + c) * 2400 + tid;
#pragma unroll
            for (int i = 0; i < 5; ++i) {
                h4_to_2ull(__ldg(&packW[bx + i * 480]), Wx[2 * i], Wx[2 * i + 1]);
                h4_to_2ull(__ldg(&packW[bh + i * 480]), Wh[2 * i], Wh[2 * i + 1]);
            }
            if (qk == 0) { bih_c = __ldg(&g3_bih[jrow]); bhh_c = __ldg(&g3_bhh[jrow]); }
        }

        /* initial staging: xin[0] from branch; hbuf[0] = S(1,t-1) */
        if (tid == 0) poll_ge(&g_flags[DONE_IDX(0, t)], FULL);
        if (t > 0 && tid == 480) poll_ge(&g_flags[DONE_IDX(1, t - 1)], FULL);
        __syncthreads();
        if (tid < 40)
            *(float4*)&xin2[tid * 4] = __ldcg((const float4*)&g_S[t * H + tid * 4]);
        if (t > 0 && !dotw) {
            const int lane = tid - 480;
            const float4* src = (const float4*)&g_S[((size_t)1 * NCH + (t - 1)) * H];
            ((float4*)hbuf)[lane] = __ldcg(src + lane);
            if (lane < 8) ((float4*)hbuf)[32 + lane] = __ldcg(src + 32 + lane);
        }
        __syncthreads();

        for (int l = 0; l < NL; ++l) {
            const int cur = l & 1, nxt = cur ^ 1;

            if (dotw) {
                /* fused X + H dots */
                const float* xv  = xin2 + cur * H + qk * HSS;
                const float* hv0 = hbuf + cur * H + qk * HSS;
                ull a0 = 0, a1 = 0, b0 = 0, b1 = 0;
#pragma unroll
                for (int i4 = 0; i4 < 5; ++i4) {
                    ulonglong2 xh = *(const ulonglong2*)(xv + i4 * 4);
                    ulonglong2 hh = *(const ulonglong2*)(hv0 + i4 * 4);
                    fma2(a0, Wx[2 * i4], xh.x); fma2(a1, Wx[2 * i4 + 1], xh.y);
                    fma2(b0, Wh[2 * i4], hh.x); fma2(b1, Wh[2 * i4 + 1], hh.y);
                }
                float ax = upsum(a0, a1);
                float ah = upsum(b0, b1);
                if (qk == 0) { ax += bih_c; ah += bhh_c; }   /* fold bias pre-reduce */

                /* prefetch l+1 weights+biases NOW (in flight during shfl+gate+barrier) */
                if (l + 1 < NL) {
                    size_t bx = (size_t)((l + 1) * 8 + c) * 2400 + tid;
                    size_t bh = (size_t)(1280 + (l + 1) * 8 + c) * 2400 + tid;
#pragma unroll
                    for (int i = 0; i < 5; ++i) {
                        h4_to_2ull(__ldg(&packW[bx + i * 480]), Wx[2 * i], Wx[2 * i + 1]);
                        h4_to_2ull(__ldg(&packW[bh + i * 480]), Wh[2 * i], Wh[2 * i + 1]);
                    }
                    if (qk == 0) {
                        bih_c = __ldg(&g3_bih[(l + 1) * H3 + jrow]);
                        bhh_c = __ldg(&g3_bhh[(l + 1) * H3 + jrow]);
                    }
                }

                ax += __shfl_xor_sync(0xffffffffu, ax, 1);
                ah += __shfl_xor_sync(0xffffffffu, ah, 1);
                ax += __shfl_xor_sync(0xffffffffu, ax, 2);
                ah += __shfl_xor_sync(0xffffffffu, ah, 2);
                ax += __shfl_xor_sync(0xffffffffu, ax, 4);
                ah += __shfl_xor_sync(0xffffffffu, ah, 4);
                if (qk == 0) { xps[q] = ax; hps[q] = ah; }
                BAR_DOT();                       /* dots -> gate (480 threads) */

                if (tid < 32) {                  /* warp 0: gate + vector push */
                    if (tid < HSS) {
                        const int i = tid;
                        float hp_i = hbuf[cur * H + c * HSS + i];
                        float r = sigm(xps[i]            + hps[i]);
                        float z = sigm(xps[HSS + i]      + hps[HSS + i]);
                        float n = tanh_f(xps[2*HSS + i]  + r * hps[2*HSS + i]);
                        float hn = (1.f - z) * n + z * hp_i;
                        xin2[nxt * H + c * HSS + i] = hn;   /* local slice */
                        __stcg(&g_S[((size_t)(l + 1) * NCH + t) * H + c * HSS + i], hn);
                        red_release(&g_flags[DONE_IDX(l + 1, t)], 1);
                    }
                    __syncwarp();
                    if (tid < 5) {               /* 5 pushers: v4 to 7 peers */
                        float4 v = *(float4*)&xin2[nxt * H + c * HSS + tid * 4];
                        uint32_t la = xin_base +
                            (uint32_t)(nxt * H + c * HSS + tid * 4) * 4u;
#pragma unroll
                        for (int r2 = 0; r2 < 8; ++r2)
                            if (r2 != c) st_cluster_f32x4(la, r2, v);
                    }
                }
                CLUSTER_ARRIVE();
                CLUSTER_WAIT();
            } else {
                /* warp15: prefetch h for layer l+1 into hbuf[nxt] */
                if (t > 0 && l + 2 <= NL) {
                    if (tid == 480) poll_ge(&g_flags[DONE_IDX(l + 2, t - 1)], FULL);
                    __syncwarp();
                    const int lane = tid - 480;
                    const float4* src =
                        (const float4*)&g_S[((size_t)(l + 2) * NCH + (t - 1)) * H];
                    ((float4*)(hbuf + nxt * H))[lane] = __ldcg(src + lane);
                    if (lane < 8)
                        ((float4*)(hbuf + nxt * H))[32 + lane] = __ldcg(src + 32 + lane);
                }
                CLUSTER_ARRIVE();
                CLUSTER_WAIT();
            }
        }
        return;
    }

    /* ============ global GRU: blocks 80..87, one cluster, 8-way ============ */
    if (blk < 88) {
        const int c = blk - 80;

        float* xp_s  = sm;                       /* [CC*RPC] 48KB */
        float* bhh_s = xp_s + CC * RPC;          /* [RPC]    */
        float* h2    = bhh_s + RPC;              /* [2][H]   */
        float* hpb   = h2 + 2 * H;               /* [RPC]    */
        const uint32_t h2_base = smem_u32(h2);

        const int q2 = tid >> 3;
        const int qk = tid & 7;
        const int j  = dotw ? ((q2 / HSS) * H + c * HSS + (q2 % HSS)) : 0;

        ull W[10];
        if (dotw) {
            const float4* wr = (const float4*)&gw_hh[(size_t)j * H + qk * HSS];
#pragma unroll
            for (int i4 = 0; i4 < 5; ++i4) {
                float4 f = __ldg(wr + i4);
                W[2 * i4] = pack2(f.x, f.y); W[2 * i4 + 1] = pack2(f.z, f.w);
            }
        }
        for (int idx = tid; idx < CC * RPC; idx += NT) {
            int s = idx / RPC, qq = idx - s * RPC;
            int jj = (qq / HSS) * H + c * HSS + (qq % HSS);
            xp_s[idx] = x[s] * gw_ih[jj] + gb_ih[jj];
        }
        if (tid < RPC) {
            int jj = (tid / HSS) * H + c * HSS + (tid % HSS);
            bhh_s[tid] = gb_hh[jj];
        }
        if (tid < 2 * H) h2[tid] = 0.f;
        __syncthreads();
        CLUSTER_SYNC();

        float hsum = 0.f;
        for (int s = 0; s < CC; ++s) {
            const int cur = s & 1, nxt = cur ^ 1;
            if (dotw) {
                const float* hv0 = h2 + cur * H + qk * HSS;
                ull a0 = 0, a1 = 0;
#pragma unroll
                for (int i4 = 0; i4 < 5; ++i4) {
                    ulonglong2 hv = *(const ulonglong2*)(hv0 + i4 * 4);
                    fma2(a0, W[2 * i4], hv.x);
                    fma2(a1, W[2 * i4 + 1], hv.y);
                }
                float a = upsum(a0, a1);
                a += __shfl_xor_sync(0xffffffffu, a, 1);
                a += __shfl_xor_sync(0xffffffffu, a, 2);
                a += __shfl_xor_sync(0xffffffffu, a, 4);
                if (qk == 0) hpb[q2] = a + bhh_s[q2];
            }
            __syncthreads();
            if (tid < HSS) {
                const float* xpt = xp_s + s * RPC;
                const int i = tid;
                float r = sigm(xpt[i]            + hpb[i]);
                float z = sigm(xpt[HSS + i]      + hpb[HSS + i]);
                float n = tanh_f(xpt[2*HSS + i]  + r * hpb[2*HSS + i]);
                float hn = (1.f - z) * n + z * h2[cur * H + c * HSS + i];
                hsum += hn;
                uint32_t a2 = h2_base + (uint32_t)(nxt * H + c * HSS + i) * 4u;
#pragma unroll
                for (int r2 = 0; r2 < 8; ++r2) st_cluster_f32(a2, r2, hn);
            }
            CLUSTER_SYNC();
        }
        if (tid < HSS) {
            __stcg(&g_xl[c * HSS + tid], hsum * (1.f / CC));
            red_release(&g_flags[GDONE_IDX], 1);
        }
        return;
    }

    /* ============ branch GRUs: blocks 88..107 (2 CTAs/branch, 4 pairs/cluster) */
    if (blk < 108) {
        const int pairblk = blk - 88;
        const int b    = pairblk >> 1;
        const int hh   = pairblk & 1;
        const int rank = pairblk & 7;

        float* xp_s = sm;                      /* [TT*240]  */
        float* h2   = xp_s + TT * 240;         /* [2][H]    */
        float* hp_s = h2 + 2 * H;              /* [240]     */
        const uint32_t h2b = smem_u32(h2);

        const int qk2 = tid & 1;
        const int gi  = tid >> 1;
        const int g   = gi / 80;
        const int ip  = gi - g * 80;
        const int jrow = dotw ? (g * H + hh * 80 + ip) : 0;

        ull W[40];
        if (dotw) {
            size_t base = (size_t)G3_U2 + (size_t)(b * 2 + hh) * 9600 + tid;
#pragma unroll
            for (int i = 0; i < 20; ++i)
                h4_to_2ull(__ldg(&packW[base + i * 480]), W[2 * i], W[2 * i + 1]);
        }
        float bhh_v = 0.f;
        if (dotw && qk2 == 0) bhh_v = __ldg(&b_bhh[b * H3 + jrow]);

        for (int idx = tid; idx < TT * 240; idx += NT) {
            int tt = idx / 240, lr = idx - tt * 240;
            int jj = (lr / 80) * H + hh * 80 + (lr % 80);
            xp_s[idx] = x[b * TT + tt] * b_wih[b * H3 + jj] + b_bih[b * H3 + jj];
        }
        if (tid < 2 * H) h2[tid] = 0.f;
        __syncthreads();
        CLUSTER_SYNC();                                    /* sync #1 */

        for (int tt = 0; tt < TT; ++tt) {
            const int cur = tt & 1, nxt = cur ^ 1;
            if (dotw) {
                const float* hv0 = h2 + cur * H + qk2 * 80;
                ull a0 = 0, a1 = 0;
#pragma unroll
                for (int i4 = 0; i4 < 20; ++i4) {
                    ulonglong2 hv = *(const ulonglong2*)(hv0 + i4 * 4);
                    fma2(a0, W[2 * i4], hv.x);
                    fma2(a1, W[2 * i4 + 1], hv.y);
                }
                float a = upsum(a0, a1);
                a += __shfl_xor_sync(0xffffffffu, a, 1);
                if (qk2 == 0) hp_s[g * 80 + ip] = a + bhh_v;
            }
            __syncthreads();

            if (dotw && qk2 == 0 && gi < 80) {
                const int i = gi;
                const float* xpt = xp_s + tt * 240;
                float r = sigm(xpt[i]          + hp_s[i]);
                float z = sigm(xpt[80 + i]     + hp_s[80 + i]);
                float n = tanh_f(xpt[160 + i]  + r * hp_s[160 + i]);
                float hn = (1.f - z) * n + z * h2[cur * H + hh * 80 + i];
                uint32_t a3 = h2b + (uint32_t)(nxt * H + hh * 80 + i) * 4u;
                st_cluster_f32(a3, rank, hn);
                st_cluster_f32(a3, rank ^ 1, hn);
            }
            CLUSTER_SYNC();                                /* syncs #2..#21 */
        }
        if (tid < 80) {
            __stcg(&g_S[b * H + hh * 80 + tid], h2[0 * H + hh * 80 + tid]);
            red_release(&g_flags[DONE_IDX(0, b)], 1);
        }
        CLUSTER_SYNC();                                    /* sync #22 */
        return;
    }

    /* ============ branch-cluster fillers: blocks 108..111 ================== */
    if (blk < 112) {
        for (int i = 0; i < TT + 2; ++i) CLUSTER_SYNC();   /* match 22 syncs */
        return;
    }

    /* ============ epilogue: block 112 (113..119 idle, no cluster ops) ====== */
    if (blk == 112) {
        if (tid == 0) {
            for (int tt = 0; tt < NCH; ++tt) poll_ge(&g_flags[DONE_IDX(NL, tt)], FULL);
            poll_ge(&g_flags[GDONE_IDX], FULL);
        }
        __syncthreads();

        float* xr = sm;
        if (tid < H) {
            float m = 0.f;
#pragma unroll
            for (int tt = 0; tt < NCH; ++tt) m += __ldcg(&g_S[(NL * NCH + tt) * H + tid]);
            m *= (1.f / NCH);
            m = fmaxf(m, 0.f);
            float xnew = __ldcg(&g_xl[tid]) * m;
            float xb = (xnew - bn_mean[tid]) * rsqrtf(bn_var[tid] + 1e-5f)
                       * bn_gamma[tid] + bn_beta[tid];
            xr[tid] = fmaxf(xb, 0.f);
        }
        __syncthreads();

        if (tid < NCLS + CC) {
            const float* wrow; float bias;
            if (tid < NCLS) { wrow = fc_w + tid * H;           bias = fc_b[tid]; }
            else            { wrow = reg_w + (tid - NCLS) * H; bias = reg_b[tid - NCLS]; }
            float a = bias;
#pragma unroll 10
            for (int k = 0; k < H; ++k) a += wrow[k] * xr[k];
            out[tid] = a;
        }
        return;
    }
}

extern "C" void kernel_launch(void* const* d_in, const int* in_sizes, int n_in,
                              void* d_out, int out_size) {
    const float* x        = (const float*)d_in[0];
    const float* b_wih    = (const float*)d_in[1];
    const float* b_whh    = (const float*)d_in[2];
    const float* b_bih    = (const float*)d_in[3];
    const float* b_bhh    = (const float*)d_in[4];
    const float* gw_ih    = (const float*)d_in[5];
    const float* gw_hh    = (const float*)d_in[6];
    const float* gb_ih    = (const float*)d_in[7];
    const float* gb_hh    = (const float*)d_in[8];
    const float* g3_wih   = (const float*)d_in[9];
    const float* g3_whh   = (const float*)d_in[10];
    const float* g3_bih   = (const float*)d_in[11];
    const float* g3_bhh   = (const float*)d_in[12];
    const float* bn_gamma = (const float*)d_in[13];
    const float* bn_beta  = (const float*)d_in[14];
    const float* bn_mean  = (const float*)d_in[15];
    const float* bn_var   = (const float*)d_in[16];
    const float* fc_w     = (const float*)d_in[17];
    const float* fc_b     = (const float*)d_in[18];
    const float* reg_w    = (const float*)d_in[19];
    const float* reg_b    = (const float*)d_in[20];
    float* out = (float*)d_out;

    /* max role smem: global GRU = CC*RPC + RPC + 2H + RPC floats (~50KB) */
    const int smem_bytes = (CC * RPC + RPC + 2 * H + RPC) * (int)sizeof(float);
    cudaFuncSetAttribute(spectral_kernel,
                         cudaFuncAttributeMaxDynamicSharedMemorySize, smem_bytes);

    pack_kernel<<<(PACK_U2 + 255) / 256, 256>>>(g3_wih, g3_whh, b_whh);
    spectral_kernel<<<NBLK, NT, smem_bytes>>>(
        x, b_wih, b_bih, b_bhh,
        gw_ih, gw_hh, gb_ih, gb_hh,
        g3_bih, g3_bhh,
        bn_gamma, bn_beta, bn_mean, bn_var,
        fc_w, fc_b, reg_w, reg_b, out);
}

// round 16
// speedup vs baseline: 1.8199x; 1.2249x over previous
#include <cuda_runtime.h>
#include <cuda_fp16.h>
#include <math.h>
#include <stdint.h>

#define H    160
#define H3   480
#define CC   200
#define TT   20
#define NCH  10
#define NL   160
#define NCLS 16
#define HSS  20          /* h-slice per CTA (8-way split) */
#define RPC  60          /* rows per CTA = 3*HSS */
#define NT   512
#define NBLK 120
#define FULL 160

#define NFLAGS ((NL + 1) * NCH + 1)
#define GDONE_IDX ((NL + 1) * NCH)
#define DONE_IDX(l, t) ((l) * NCH + (t))

/* fp16 packed weights, uint2 = 4 halfs.
   g3 wih chunks [0,1280), g3 whh chunks [1280,2560), branch after.
   g3 chunk = 2400 uint2 (480 tid x 5 i4); branch chunk = 9600 (480 x 20). */
#define G3_U2   (2560 * 2400)
#define BR_U2   (20 * 9600)
#define PACK_U2 (G3_U2 + BR_U2)

__device__ uint2  g_pack[PACK_U2];          /* ~50.7 MB */
__device__ float  g_S[(NL + 1) * NCH * H];
__device__ float  g_xl[H];
__device__ int    g_flags[NFLAGS];

typedef unsigned long long ull;

__device__ __forceinline__ float sigm(float v)   { return __fdividef(1.f, 1.f + __expf(-v)); }
__device__ __forceinline__ float tanh_f(float v) { return __fdividef(2.f, 1.f + __expf(-2.f * v)) - 1.f; }

__device__ __forceinline__ void poll_ge(const int* f, int tgt) {
    int v;
    do {
        asm volatile("ld.acquire.gpu.s32 %0, [%1];" : "=r"(v) : "l"(f) : "memory");
    } while (v < tgt);
}
__device__ __forceinline__ void red_release(int* f, int val) {
    asm volatile("red.release.gpu.add.s32 [%0], %1;" :: "l"(f), "r"(val) : "memory");
}
__device__ __forceinline__ uint32_t smem_u32(const void* p) {
    uint32_t a;
    asm("{ .reg .u64 t; cvta.to.shared.u64 t, %1; cvt.u32.u64 %0, t; }" : "=r"(a) : "l"(p));
    return a;
}
__device__ __forceinline__ void st_cluster_f32(uint32_t laddr, int rank, float v) {
    uint32_t r;
    asm("mapa.shared::cluster.u32 %0, %1, %2;" : "=r"(r) : "r"(laddr), "r"(rank));
    asm volatile("st.shared::cluster.f32 [%0], %1;" :: "r"(r), "f"(v) : "memory");
}
__device__ __forceinline__ void st_cluster_f32x4(uint32_t laddr, int rank, float4 v) {
    uint32_t r;
    asm("mapa.shared::cluster.u32 %0, %1, %2;" : "=r"(r) : "r"(laddr), "r"(rank));
    asm volatile("st.shared::cluster.v4.f32 [%0], {%1, %2, %3, %4};"
                 :: "r"(r), "f"(v.x), "f"(v.y), "f"(v.z), "f"(v.w) : "memory");
}
#define CLUSTER_SYNC() do { \
    asm volatile("barrier.cluster.arrive.aligned;" ::: "memory"); \
    asm volatile("barrier.cluster.wait.aligned;"   ::: "memory"); } while (0)
#define CLUSTER_ARRIVE() asm volatile("barrier.cluster.arrive;" ::: "memory")
#define CLUSTER_WAIT()   asm volatile("barrier.cluster.wait;"   ::: "memory")
#define BAR_DOT()        asm volatile("bar.sync 1, 480;" ::: "memory")

__device__ __forceinline__ ull pack2(float x, float y) {
    ull u; asm("mov.b64 %0, {%1, %2};" : "=l"(u) : "f"(x), "f"(y)); return u;
}
__device__ __forceinline__ void fma2(ull& acc, ull a, ull b) {
    asm("fma.rn.f32x2 %0, %1, %2, %0;" : "+l"(acc) : "l"(a), "l"(b));
}
__device__ __forceinline__ float upsum(ull a0, ull a1) {
    float l0, h0, l1, h1;
    asm("mov.b64 {%0, %1}, %2;" : "=f"(l0), "=f"(h0) : "l"(a0));
    asm("mov.b64 {%0, %1}, %2;" : "=f"(l1), "=f"(h1) : "l"(a1));
    return (l0 + h0) + (l1 + h1);
}
__device__ __forceinline__ void h4_to_2ull(uint2 r, ull& a, ull& b) {
    __half2 h0, h1;
    *(uint32_t*)&h0 = r.x; *(uint32_t*)&h1 = r.y;
    float2 f0 = __half22float2(h0), f1 = __half22float2(h1);
    a = pack2(f0.x, f0.y); b = pack2(f1.x, f1.y);
}

/* ---------- pack kernel (fp16, also zeroes flags) ---------- */
__global__ void pack_kernel(const float* __restrict__ wih,
                            const float* __restrict__ whh,
                            const float* __restrict__ bwhh) {
    int id = blockIdx.x * blockDim.x + threadIdx.x;
    if (id < NFLAGS) g_flags[id] = 0;
    if (id >= PACK_U2) return;
    float4 f;
    if (id < G3_U2) {
        int chunkid = id / 2400;
        int within  = id - chunkid * 2400;
        int i4 = within / 480, tid = within - i4 * 480;
        int m  = chunkid / 1280;
        int lc = chunkid - m * 1280;
        int l = lc >> 3, c = lc & 7;
        int q = tid >> 3, qk = tid & 7;
        int jrow = (q / HSS) * H + c * HSS + (q % HSS);
        int k = qk * 20 + i4 * 4;
        const float* src = (m == 0) ? wih : whh;
        f = *(const float4*)(src + ((size_t)l * H3 + jrow) * H + k);
    } else {
        int id2    = id - G3_U2;
        int chunk  = id2 / 9600;
        int within = id2 - chunk * 9600;
        int i4 = within / 480, tid = within - i4 * 480;
        int b = chunk >> 1, hh = chunk & 1;
        int qk2 = tid & 1, gi = tid >> 1;
        int g = gi / 80, ip = gi - g * 80;
        int j = g * H + hh * 80 + ip;
        int k = qk2 * 80 + i4 * 4;
        f = *(const float4*)(bwhh + ((size_t)b * H3 + j) * H + k);
    }
    __half2 h01 = __floats2half2_rn(f.x, f.y);
    __half2 h23 = __floats2half2_rn(f.z, f.w);
    uint2 v;
    v.x = *(uint32_t*)&h01;
    v.y = *(uint32_t*)&h23;
    g_pack[id] = v;
}

/* ---------- main persistent kernel ---------- */
__global__ void __launch_bounds__(NT, 1) __cluster_dims__(8, 1, 1)
spectral_kernel(
    const float* __restrict__ x,
    const float* __restrict__ b_wih, const float* __restrict__ b_bih,
    const float* __restrict__ b_bhh,
    const float* __restrict__ gw_ih, const float* __restrict__ gw_hh,
    const float* __restrict__ gb_ih, const float* __restrict__ gb_hh,
    const float* __restrict__ g3_bih, const float* __restrict__ g3_bhh,
    const float* __restrict__ bn_gamma, const float* __restrict__ bn_beta,
    const float* __restrict__ bn_mean, const float* __restrict__ bn_var,
    const float* __restrict__ fc_w, const float* __restrict__ fc_b,
    const float* __restrict__ reg_w, const float* __restrict__ reg_b,
    float* __restrict__ out)
{
    extern __shared__ float sm[];
    const int tid = threadIdx.x;
    const int blk = blockIdx.x;
    const uint2* packW = g_pack;
    const bool dotw = (tid < 480);

    /* ============ g3 wavefront: blocks 0..79 (cluster of 8 = time group) === */
    if (blk < 80) {
        const int t = blk >> 3;
        const int c = blk & 7;
        const int q  = tid >> 3;          /* 0..59  row within CTA slice */
        const int qk = tid & 7;           /* 0..7   k-eighth (20 elems)  */
        const int jrow = dotw ? ((q / HSS) * H + c * HSS + (q % HSS)) : 0;

        float* xin2 = sm;                 /* [2][H] */
        float* hbuf = sm + 2 * H;         /* [2][H] double-buffered h_prev */
        float* xps  = sm + 4 * H;         /* [RPC]  */
        float* hps  = xps + RPC;          /* [RPC]  */
        const uint32_t xin_base = smem_u32(xin2);

        if (tid < 2 * H) hbuf[tid] = 0.f;
        CLUSTER_SYNC();   /* siblings alive + hbuf zeroed */

        ull Wx[10], Wh[10];
        float bih_c = 0.f, bhh_c = 0.f;
        if (dotw) {   /* preload wih(0), whh(0), biases(0) */
            size_t bx = (size_t)(0 * 8 + c) * 2400 + tid;
            size_t bh = (size_t)(1280 + 0 * 8 + c) * 2400 + tid;
#pragma unroll
            for (int i = 0; i < 5; ++i) {
                h4_to_2ull(__ldg(&packW[bx + i * 480]), Wx[2 * i], Wx[2 * i + 1]);
                h4_to_2ull(__ldg(&packW[bh + i * 480]), Wh[2 * i], Wh[2 * i + 1]);
            }
            if (qk == 0) { bih_c = __ldg(&g3_bih[jrow]); bhh_c = __ldg(&g3_bhh[jrow]); }
        }

        /* initial staging: xin[0] from branch; hbuf[0] = S(1,t-1) */
        if (tid == 0) poll_ge(&g_flags[DONE_IDX(0, t)], FULL);
        if (t > 0 && tid == 480) poll_ge(&g_flags[DONE_IDX(1, t - 1)], FULL);
        __syncthreads();
        if (tid < 40)
            *(float4*)&xin2[tid * 4] = __ldcg((const float4*)&g_S[t * H + tid * 4]);
        if (t > 0 && !dotw) {
            const int lane = tid - 480;
            const float4* src = (const float4*)&g_S[((size_t)1 * NCH + (t - 1)) * H];
            ((float4*)hbuf)[lane] = __ldcg(src + lane);
            if (lane < 8) ((float4*)hbuf)[32 + lane] = __ldcg(src + 32 + lane);
        }
        __syncthreads();

        for (int l = 0; l < NL; ++l) {
            const int cur = l & 1, nxt = cur ^ 1;

            if (dotw) {
                /* fused X + H dots */
                const float* xv  = xin2 + cur * H + qk * HSS;
                const float* hv0 = hbuf + cur * H + qk * HSS;
                ull a0 = 0, a1 = 0, b0 = 0, b1 = 0;
#pragma unroll
                for (int i4 = 0; i4 < 5; ++i4) {
                    ulonglong2 xh = *(const ulonglong2*)(xv + i4 * 4);
                    ulonglong2 hh = *(const ulonglong2*)(hv0 + i4 * 4);
                    fma2(a0, Wx[2 * i4], xh.x); fma2(a1, Wx[2 * i4 + 1], xh.y);
                    fma2(b0, Wh[2 * i4], hh.x); fma2(b1, Wh[2 * i4 + 1], hh.y);
                }
                float ax = upsum(a0, a1);
                float ah = upsum(b0, b1);
                if (qk == 0) { ax += bih_c; ah += bhh_c; }   /* fold bias pre-reduce */

                ax += __shfl_xor_sync(0xffffffffu, ax, 1);
                ah += __shfl_xor_sync(0xffffffffu, ah, 1);
                ax += __shfl_xor_sync(0xffffffffu, ax, 2);
                ah += __shfl_xor_sync(0xffffffffu, ah, 2);
                ax += __shfl_xor_sync(0xffffffffu, ax, 4);
                ah += __shfl_xor_sync(0xffffffffu, ah, 4);
                if (qk == 0) { xps[q] = ax; hps[q] = ah; }
                BAR_DOT();                       /* dots -> gate (480 threads) */

                if (tid < 32) {                  /* warp 0: gate + vector push */
                    if (tid < HSS) {
                        const int i = tid;
                        float hp_i = hbuf[cur * H + c * HSS + i];
                        float r = sigm(xps[i]            + hps[i]);
                        float z = sigm(xps[HSS + i]      + hps[HSS + i]);
                        float n = tanh_f(xps[2*HSS + i]  + r * hps[2*HSS + i]);
                        float hn = (1.f - z) * n + z * hp_i;
                        xin2[nxt * H + c * HSS + i] = hn;   /* local slice */
                        __stcg(&g_S[((size_t)(l + 1) * NCH + t) * H + c * HSS + i], hn);
                        red_release(&g_flags[DONE_IDX(l + 1, t)], 1);
                    }
                    __syncwarp();
                    if (tid < 5) {               /* 5 pushers: v4 to 7 peers */
                        float4 v = *(float4*)&xin2[nxt * H + c * HSS + tid * 4];
                        uint32_t la = xin_base +
                            (uint32_t)(nxt * H + c * HSS + tid * 4) * 4u;
#pragma unroll
                        for (int r2 = 0; r2 < 8; ++r2)
                            if (r2 != c) st_cluster_f32x4(la, r2, v);
                    }
                }
                CLUSTER_ARRIVE();
                /* prefetch + convert l+1 weights BETWEEN arrive and wait:
                   the load-dependency stall overlaps the barrier wait (R10 slot) */
                if (l + 1 < NL) {
                    size_t bx = (size_t)((l + 1) * 8 + c) * 2400 + tid;
                    size_t bh = (size_t)(1280 + (l + 1) * 8 + c) * 2400 + tid;
#pragma unroll
                    for (int i = 0; i < 5; ++i) {
                        h4_to_2ull(__ldg(&packW[bx + i * 480]), Wx[2 * i], Wx[2 * i + 1]);
                        h4_to_2ull(__ldg(&packW[bh + i * 480]), Wh[2 * i], Wh[2 * i + 1]);
                    }
                    if (qk == 0) {
                        bih_c = __ldg(&g3_bih[(l + 1) * H3 + jrow]);
                        bhh_c = __ldg(&g3_bhh[(l + 1) * H3 + jrow]);
                    }
                }
                CLUSTER_WAIT();
            } else {
                /* warp15: prefetch h for layer l+1 into hbuf[nxt] */
                if (t > 0 && l + 2 <= NL) {
                    if (tid == 480) poll_ge(&g_flags[DONE_IDX(l + 2, t - 1)], FULL);
                    __syncwarp();
                    const int lane = tid - 480;
                    const float4* src =
                        (const float4*)&g_S[((size_t)(l + 2) * NCH + (t - 1)) * H];
                    ((float4*)(hbuf + nxt * H))[lane] = __ldcg(src + lane);
                    if (lane < 8)
                        ((float4*)(hbuf + nxt * H))[32 + lane] = __ldcg(src + 32 + lane);
                }
                CLUSTER_ARRIVE();
                CLUSTER_WAIT();
            }
        }
        return;
    }

    /* ============ global GRU: blocks 80..87, one cluster, 8-way ============ */
    if (blk < 88) {
        const int c = blk - 80;

        float* xp_s  = sm;                       /* [CC*RPC] 48KB */
        float* bhh_s = xp_s + CC * RPC;          /* [RPC]    */
        float* h2    = bhh_s + RPC;              /* [2][H]   */
        float* hpb   = h2 + 2 * H;               /* [RPC]    */
        const uint32_t h2_base = smem_u32(h2);

        const int q2 = tid >> 3;
        const int qk = tid & 7;
        const int j  = dotw ? ((q2 / HSS) * H + c * HSS + (q2 % HSS)) : 0;

        ull W[10];
        if (dotw) {
            const float4* wr = (const float4*)&gw_hh[(size_t)j * H + qk * HSS];
#pragma unroll
            for (int i4 = 0; i4 < 5; ++i4) {
                float4 f = __ldg(wr + i4);
                W[2 * i4] = pack2(f.x, f.y); W[2 * i4 + 1] = pack2(f.z, f.w);
            }
        }
        for (int idx = tid; idx < CC * RPC; idx += NT) {
            int s = idx / RPC, qq = idx - s * RPC;
            int jj = (qq / HSS) * H + c * HSS + (qq % HSS);
            xp_s[idx] = x[s] * gw_ih[jj] + gb_ih[jj];
        }
        if (tid < RPC) {
            int jj = (tid / HSS) * H + c * HSS + (tid % HSS);
            bhh_s[tid] = gb_hh[jj];
        }
        if (tid < 2 * H) h2[tid] = 0.f;
        __syncthreads();
        CLUSTER_SYNC();

        float hsum = 0.f;
        for (int s = 0; s < CC; ++s) {
            const int cur = s & 1, nxt = cur ^ 1;
            if (dotw) {
                const float* hv0 = h2 + cur * H + qk * HSS;
                ull a0 = 0, a1 = 0;
#pragma unroll
                for (int i4 = 0; i4 < 5; ++i4) {
                    ulonglong2 hv = *(const ulonglong2*)(hv0 + i4 * 4);
                    fma2(a0, W[2 * i4], hv.x);
                    fma2(a1, W[2 * i4 + 1], hv.y);
                }
                float a = upsum(a0, a1);
                a += __shfl_xor_sync(0xffffffffu, a, 1);
                a += __shfl_xor_sync(0xffffffffu, a, 2);
                a += __shfl_xor_sync(0xffffffffu, a, 4);
                if (qk == 0) hpb[q2] = a + bhh_s[q2];
            }
            __syncthreads();
            if (tid < HSS) {
                const float* xpt = xp_s + s * RPC;
                const int i = tid;
                float r = sigm(xpt[i]            + hpb[i]);
                float z = sigm(xpt[HSS + i]      + hpb[HSS + i]);
                float n = tanh_f(xpt[2*HSS + i]  + r * hpb[2*HSS + i]);
                float hn = (1.f - z) * n + z * h2[cur * H + c * HSS + i];
                hsum += hn;
                uint32_t a2 = h2_base + (uint32_t)(nxt * H + c * HSS + i) * 4u;
#pragma unroll
                for (int r2 = 0; r2 < 8; ++r2) st_cluster_f32(a2, r2, hn);
            }
            CLUSTER_SYNC();
        }
        if (tid < HSS) {
            __stcg(&g_xl[c * HSS + tid], hsum * (1.f / CC));
            red_release(&g_flags[GDONE_IDX], 1);
        }
        return;
    }

    /* ============ branch GRUs: blocks 88..107 (2 CTAs/branch, 4 pairs/cluster) */
    if (blk < 108) {
        const int pairblk = blk - 88;
        const int b    = pairblk >> 1;
        const int hh   = pairblk & 1;
        const int rank = pairblk & 7;

        float* xp_s = sm;                      /* [TT*240]  */
        float* h2   = xp_s + TT * 240;         /* [2][H]    */
        float* hp_s = h2 + 2 * H;              /* [240]     */
        const uint32_t h2b = smem_u32(h2);

        const int qk2 = tid & 1;
        const int gi  = tid >> 1;
        const int g   = gi / 80;
        const int ip  = gi - g * 80;
        const int jrow = dotw ? (g * H + hh * 80 + ip) : 0;

        ull W[40];
        if (dotw) {
            size_t base = (size_t)G3_U2 + (size_t)(b * 2 + hh) * 9600 + tid;
#pragma unroll
            for (int i = 0; i < 20; ++i)
                h4_to_2ull(__ldg(&packW[base + i * 480]), W[2 * i], W[2 * i + 1]);
        }
        float bhh_v = 0.f;
        if (dotw && qk2 == 0) bhh_v = __ldg(&b_bhh[b * H3 + jrow]);

        for (int idx = tid; idx < TT * 240; idx += NT) {
            int tt = idx / 240, lr = idx - tt * 240;
            int jj = (lr / 80) * H + hh * 80 + (lr % 80);
            xp_s[idx] = x[b * TT + tt] * b_wih[b * H3 + jj] + b_bih[b * H3 + jj];
        }
        if (tid < 2 * H) h2[tid] = 0.f;
        __syncthreads();
        CLUSTER_SYNC();                                    /* sync #1 */

        for (int tt = 0; tt < TT; ++tt) {
            const int cur = tt & 1, nxt = cur ^ 1;
            if (dotw) {
                const float* hv0 = h2 + cur * H + qk2 * 80;
                ull a0 = 0, a1 = 0;
#pragma unroll
                for (int i4 = 0; i4 < 20; ++i4) {
                    ulonglong2 hv = *(const ulonglong2*)(hv0 + i4 * 4);
                    fma2(a0, W[2 * i4], hv.x);
                    fma2(a1, W[2 * i4 + 1], hv.y);
                }
                float a = upsum(a0, a1);
                a += __shfl_xor_sync(0xffffffffu, a, 1);
                if (qk2 == 0) hp_s[g * 80 + ip] = a + bhh_v;
            }
            __syncthreads();

            if (dotw && qk2 == 0 && gi < 80) {
                const int i = gi;
                const float* xpt = xp_s + tt * 240;
                float r = sigm(xpt[i]          + hp_s[i]);
                float z = sigm(xpt[80 + i]     + hp_s[80 + i]);
                float n = tanh_f(xpt[160 + i]  + r * hp_s[160 + i]);
                float hn = (1.f - z) * n + z * h2[cur * H + hh * 80 + i];
                uint32_t a3 = h2b + (uint32_t)(nxt * H + hh * 80 + i) * 4u;
                st_cluster_f32(a3, rank, hn);
                st_cluster_f32(a3, rank ^ 1, hn);
            }
            CLUSTER_SYNC();                                /* syncs #2..#21 */
        }
        if (tid < 80) {
            __stcg(&g_S[b * H + hh * 80 + tid], h2[0 * H + hh * 80 + tid]);
            red_release(&g_flags[DONE_IDX(0, b)], 1);
        }
        CLUSTER_SYNC();                                    /* sync #22 */
        return;
    }

    /* ============ branch-cluster fillers: blocks 108..111 ================== */
    if (blk < 112) {
        for (int i = 0; i < TT + 2; ++i) CLUSTER_SYNC();   /* match 22 syncs */
        return;
    }

    /* ============ epilogue: block 112 (113..119 idle, no cluster ops) ====== */
    if (blk == 112) {
        if (tid == 0) {
            for (int tt = 0; tt < NCH; ++tt) poll_ge(&g_flags[DONE_IDX(NL, tt)], FULL);
            poll_ge(&g_flags[GDONE_IDX], FULL);
        }
        __syncthreads();

        float* xr = sm;
        if (tid < H) {
            float m = 0.f;
#pragma unroll
            for (int tt = 0; tt < NCH; ++tt) m += __ldcg(&g_S[(NL * NCH + tt) * H + tid]);
            m *= (1.f / NCH);
            m = fmaxf(m, 0.f);
            float xnew = __ldcg(&g_xl[tid]) * m;
            float xb = (xnew - bn_mean[tid]) * rsqrtf(bn_var[tid] + 1e-5f)
                       * bn_gamma[tid] + bn_beta[tid];
            xr[tid] = fmaxf(xb, 0.f);
        }
        __syncthreads();

        if (tid < NCLS + CC) {
            const float* wrow; float bias;
            if (tid < NCLS) { wrow = fc_w + tid * H;           bias = fc_b[tid]; }
            else            { wrow = reg_w + (tid - NCLS) * H; bias = reg_b[tid - NCLS]; }
            float a = bias;
#pragma unroll 10
            for (int k = 0; k < H; ++k) a += wrow[k] * xr[k];
            out[tid] = a;
        }
        return;
    }
}

extern "C" void kernel_launch(void* const* d_in, const int* in_sizes, int n_in,
                              void* d_out, int out_size) {
    const float* x        = (const float*)d_in[0];
    const float* b_wih    = (const float*)d_in[1];
    const float* b_whh    = (const float*)d_in[2];
    const float* b_bih    = (const float*)d_in[3];
    const float* b_bhh    = (const float*)d_in[4];
    const float* gw_ih    = (const float*)d_in[5];
    const float* gw_hh    = (const float*)d_in[6];
    const float* gb_ih    = (const float*)d_in[7];
    const float* gb_hh    = (const float*)d_in[8];
    const float* g3_wih   = (const float*)d_in[9];
    const float* g3_whh   = (const float*)d_in[10];
    const float* g3_bih   = (const float*)d_in[11];
    const float* g3_bhh   = (const float*)d_in[12];
    const float* bn_gamma = (const float*)d_in[13];
    const float* bn_beta  = (const float*)d_in[14];
    const float* bn_mean  = (const float*)d_in[15];
    const float* bn_var   = (const float*)d_in[16];
    const float* fc_w     = (const float*)d_in[17];
    const float* fc_b     = (const float*)d_in[18];
    const float* reg_w    = (const float*)d_in[19];
    const float* reg_b    = (const float*)d_in[20];
    float* out = (float*)d_out;

    /* max role smem: global GRU = CC*RPC + RPC + 2H + RPC floats (~50KB) */
    const int smem_bytes = (CC * RPC + RPC + 2 * H + RPC) * (int)sizeof(float);
    cudaFuncSetAttribute(spectral_kernel,
                         cudaFuncAttributeMaxDynamicSharedMemorySize, smem_bytes);

    pack_kernel<<<(PACK_U2 + 255) / 256, 256>>>(g3_wih, g3_whh, b_whh);
    spectral_kernel<<<NBLK, NT, smem_bytes>>>(
        x, b_wih, b_bih, b_bhh,
        gw_ih, gw_hh, gb_ih, gb_hh,
        g3_bih, g3_bhh,
        bn_gamma, bn_beta, bn_mean, bn_var,
        fc_w, fc_b, reg_w, reg_b, out);
}